// round 13
// baseline (speedup 1.0000x reference)
#include <cuda_runtime.h>
#include <cstdint>

#define NN 100000
#define NE 1000000
#define HD 64
#define NG 1000
#define NH 4
#define NO 128

// ---------------- scratch (device globals; no allocation) ----------------
static __device__ float g_h[NN * HD];
static __device__ float g_agg[NN * HD];
static __device__ float g_z[NN * HD];
static __device__ float g_red[2 * HD];     // zero at entry; finalize re-zeroes
static __device__ float g_bns[2 * HD];     // BN scale, 2 slots
static __device__ float g_bnt[2 * HD];     // BN shift, 2 slots
static __device__ float g_sc[NN * NH];
static __device__ float g_pool[NG * HD];
// CSR scratch
static __device__ int g_deg[NN];
static __device__ int g_incl[NN];
static __device__ int g_off[NN + 1];
static __device__ int g_cur[NN];
static __device__ int g_bsum[128];
static __device__ int g_bpre[128];
static __device__ int g_esrc[NE];
static __device__ int g_goff[NG + 1];

// ---------------- f32x2 packed FMA helpers ----------------
__device__ __forceinline__ void ffma2(unsigned long long& d,
                                      unsigned long long a,
                                      unsigned long long b) {
    asm("fma.rn.f32x2 %0, %1, %2, %0;" : "+l"(d) : "l"(a), "l"(b));
}
__device__ __forceinline__ unsigned long long bcast2(float x) {
    unsigned long long r;
    asm("mov.b64 %0, {%1, %1};" : "=l"(r) : "f"(x));
    return r;
}
__device__ __forceinline__ uint32_t smem_u32(const void* p) {
    uint32_t a;
    asm("{ .reg .u64 t; cvta.to.shared.u64 t, %1; cvt.u32.u64 %0, t; }"
        : "=r"(a) : "l"(p));
    return a;
}
// async 16B copy; src_size=0 zero-fills
__device__ __forceinline__ void cpasync16(uint32_t dst, const void* src,
                                          int src_size) {
    asm volatile("cp.async.ca.shared.global [%0], [%1], 16, %2;"
                 :: "r"(dst), "l"(src), "r"(src_size) : "memory");
}
__device__ __forceinline__ void cpasync_wait_all() {
    asm volatile("cp.async.commit_group;" ::: "memory");
    asm volatile("cp.async.wait_group 0;" ::: "memory");
}

// ---------------- BatchNorm ----------------
__global__ void k_bn_stats(const float* __restrict__ Z) {
    int f = threadIdx.x & 63;
    int rl = threadIdx.x >> 6;
    float s = 0.f, q = 0.f;
    for (int r = blockIdx.x * 4 + rl; r < NN; r += gridDim.x * 4) {
        float v = Z[(size_t)r * HD + f];
        s += v;
        q += v * v;
    }
    __shared__ float sh[512];
    sh[threadIdx.x] = s;
    sh[256 + threadIdx.x] = q;
    __syncthreads();
    if (rl == 0) {
        s = sh[f] + sh[64 + f] + sh[128 + f] + sh[192 + f];
        q = sh[256 + f] + sh[320 + f] + sh[384 + f] + sh[448 + f];
        atomicAdd(&g_red[f], s);
        atomicAdd(&g_red[64 + f], q);
    }
}

// computes BN scale/shift into slot, then zeroes g_red (keeps invariant)
__global__ void k_bn_finalize(const float* __restrict__ gamma,
                              const float* __restrict__ beta, int slot) {
    int f = threadIdx.x;  // 64 threads
    float inv_n = 1.f / (float)NN;
    float mu = g_red[f] * inv_n;
    float var = fmaxf(g_red[64 + f] * inv_n - mu * mu, 0.f);
    float rs = rsqrtf(var + 1e-5f);
    float sc = rs * gamma[f];
    g_bns[slot * 64 + f] = sc;
    g_bnt[slot * 64 + f] = beta[f] - mu * sc;
    g_red[f] = 0.f;
    g_red[64 + f] = 0.f;
}

// h = relu(z*s1+t1) + h   (slot 1; res == h invariant)
__global__ void k_resid_fused() {
    int t = blockIdx.x * blockDim.x + threadIdx.x;
    if (t >= NN * 16) return;
    int c4 = t & 15;
    float4 s = ((const float4*)(g_bns + 64))[c4];
    float4 b = ((const float4*)(g_bnt + 64))[c4];
    float4 v = ((const float4*)g_z)[t];
    float4 r = ((const float4*)g_h)[t];
    float4 a;
    a.x = fmaxf(v.x * s.x + b.x, 0.f) + r.x;
    a.y = fmaxf(v.y * s.y + b.y, 0.f) + r.y;
    a.z = fmaxf(v.z * s.z + b.z, 0.f) + r.z;
    a.w = fmaxf(v.w * s.w + b.w, 0.f) + r.w;
    ((float4*)g_h)[t] = a;
}

// ---------------- CSR build ----------------
__global__ void k_deg_zero() {
    int i = blockIdx.x * blockDim.x + threadIdx.x;
    if (i < NN) g_deg[i] = 0;
}

__global__ void k_csr_count(const int* __restrict__ dst) {
    int e = blockIdx.x * blockDim.x + threadIdx.x;
    if (e < NE) atomicAdd(&g_deg[dst[e]], 1);
}

__global__ void k_scan_chunk() {
    __shared__ int ssum[256];
    int blk = blockIdx.x;
    int base = blk * 1024;
    int tid = threadIdx.x;
    int v[4];
    int s = 0;
#pragma unroll
    for (int j = 0; j < 4; j++) {
        int idx = base + tid * 4 + j;
        int d = (idx < NN) ? g_deg[idx] : 0;
        v[j] = d;
        s += d;
    }
    ssum[tid] = s;
    __syncthreads();
    for (int o = 1; o < 256; o <<= 1) {
        int x = (tid >= o) ? ssum[tid - o] : 0;
        __syncthreads();
        ssum[tid] += x;
        __syncthreads();
    }
    int run = ssum[tid] - s;
#pragma unroll
    for (int j = 0; j < 4; j++) {
        run += v[j];
        int idx = base + tid * 4 + j;
        if (idx < NN) g_incl[idx] = run;
    }
    if (tid == 255) g_bsum[blk] = ssum[255];
}

__global__ void k_scan_tops(int nchunks) {
    __shared__ int sh[128];
    int tid = threadIdx.x;
    int v = (tid < nchunks) ? g_bsum[tid] : 0;
    sh[tid] = v;
    __syncthreads();
    for (int o = 1; o < 128; o <<= 1) {
        int x = (tid >= o) ? sh[tid - o] : 0;
        __syncthreads();
        sh[tid] += x;
        __syncthreads();
    }
    g_bpre[tid] = sh[tid] - v;
}

__global__ void k_scan_final() {
    int i = blockIdx.x * blockDim.x + threadIdx.x;
    if (i == 0) g_off[0] = 0;
    if (i < NN) {
        int off_ip1 = g_incl[i] + g_bpre[i >> 10];
        g_off[i + 1] = off_ip1;
        int off_i = (i == 0) ? 0 : (g_incl[i - 1] + g_bpre[(i - 1) >> 10]);
        g_cur[i] = off_i;
    }
}

__global__ void k_csr_fill(const int* __restrict__ src,
                           const int* __restrict__ dst) {
    int e = blockIdx.x * blockDim.x + threadIdx.x;
    if (e >= NE) return;
    int d = dst[e];
    int pos = atomicAdd(&g_cur[d], 1);
    g_esrc[pos] = src[e];
}

__global__ void k_goff(const int* __restrict__ batch) {
    int i = blockIdx.x * blockDim.x + threadIdx.x;
    if (i >= NN) return;
    int b = batch[i];
    if (i == 0) {
        for (int g = 0; g <= b; g++) g_goff[g] = 0;
    } else {
        int p = batch[i - 1];
        for (int g = p + 1; g <= b; g++) g_goff[g] = i;
    }
    if (i == NN - 1) {
        for (int g = b + 1; g <= NG; g++) g_goff[g] = NN;
    }
}

// ---- gather: agg[n] = f(X[n]) + sum f(X[src]); f = affine+relu if aff ----
__device__ __forceinline__ float4 xf4(float4 v, float4 s, float4 b, int aff) {
    if (!aff) return v;
    float4 o;
    o.x = fmaxf(v.x * s.x + b.x, 0.f);
    o.y = fmaxf(v.y * s.y + b.y, 0.f);
    o.z = fmaxf(v.z * s.z + b.z, 0.f);
    o.w = fmaxf(v.w * s.w + b.w, 0.f);
    return o;
}

__global__ void k_gather(const float* __restrict__ X, int aff) {
    int t = blockIdx.x * blockDim.x + threadIdx.x;
    int n = t >> 4;
    if (n >= NN) return;
    int l = t & 15;
    float4 s = make_float4(1.f, 1.f, 1.f, 1.f);
    float4 b = make_float4(0.f, 0.f, 0.f, 0.f);
    if (aff) {  // slot 0
        s = ((const float4*)g_bns)[l];
        b = ((const float4*)g_bnt)[l];
    }
    int beg = g_off[n], end = g_off[n + 1];
    float4 acc = xf4(((const float4*)X)[(size_t)n * 16 + l], s, b, aff);
    int e = beg;
    for (; e + 8 <= end; e += 8) {
        int si[8];
#pragma unroll
        for (int j = 0; j < 8; j++) si[j] = __ldg(&g_esrc[e + j]);
        float4 v[8];
#pragma unroll
        for (int j = 0; j < 8; j++)
            v[j] = ((const float4*)X)[(size_t)si[j] * 16 + l];
#pragma unroll
        for (int j = 0; j < 8; j++) {
            float4 w = xf4(v[j], s, b, aff);
            acc.x += w.x; acc.y += w.y; acc.z += w.z; acc.w += w.w;
        }
    }
    for (; e + 4 <= end; e += 4) {
        int s0 = __ldg(&g_esrc[e + 0]);
        int s1 = __ldg(&g_esrc[e + 1]);
        int s2 = __ldg(&g_esrc[e + 2]);
        int s3 = __ldg(&g_esrc[e + 3]);
        float4 v0 = ((const float4*)X)[(size_t)s0 * 16 + l];
        float4 v1 = ((const float4*)X)[(size_t)s1 * 16 + l];
        float4 v2 = ((const float4*)X)[(size_t)s2 * 16 + l];
        float4 v3 = ((const float4*)X)[(size_t)s3 * 16 + l];
        v0 = xf4(v0, s, b, aff);
        v1 = xf4(v1, s, b, aff);
        v2 = xf4(v2, s, b, aff);
        v3 = xf4(v3, s, b, aff);
        acc.x += v0.x + v1.x + v2.x + v3.x;
        acc.y += v0.y + v1.y + v2.y + v3.y;
        acc.z += v0.z + v1.z + v2.z + v3.z;
        acc.w += v0.w + v1.w + v2.w + v3.w;
    }
    for (; e < end; e++) {
        int si = __ldg(&g_esrc[e]);
        float4 v = xf4(((const float4*)X)[(size_t)si * 16 + l], s, b, aff);
        acc.x += v.x; acc.y += v.y; acc.z += v.z; acc.w += v.w;
    }
    ((float4*)g_agg)[(size_t)n * 16 + l] = acc;
}

// ---------------- GEMM: Y = op(X) @ W + b ----------------
// 128-row tile x 64 cols, 128 threads, 8x8 micro-tile, packed f32x2 FMA.
// Tile + W loads via cp.async (LDGSTS) when no input affine.
__global__ void __launch_bounds__(128, 4)
gemm128(const float* __restrict__ X, const float* __restrict__ W,
        const float* __restrict__ bias, float* __restrict__ Y, int M, int relu,
        const float* __restrict__ inscale, const float* __restrict__ inshift,
        int bnstat, const float* __restrict__ seed, float* __restrict__ scout) {
    __shared__ float Ws[64 * 64];
    __shared__ float Xs[128 * 64];
    int tid = threadIdx.x;
    int row0 = blockIdx.x << 7;

    // W load: always async (contiguous, no transform)
    {
        const float4* W4 = (const float4*)W;
        uint32_t wbase = smem_u32(Ws);
#pragma unroll
        for (int i = 0; i < 8; i++)
            cpasync16(wbase + (tid + 128 * i) * 16, W4 + tid + 128 * i, 16);
    }
    // X tile load
    {
        int c4 = tid & 15;
        int r0 = tid >> 4;
        if (!inscale) {
            uint32_t xbase = smem_u32(Xs);
#pragma unroll
            for (int i = 0; i < 16; i++) {
                int m = r0 + 8 * i;
                int row = row0 + m;
                int cs = (c4 ^ (m >> 3)) & 15;
                cpasync16(xbase + (m * 64 + cs * 4) * 4,
                          (const float4*)X + (size_t)row * 16 + c4,
                          (row < M) ? 16 : 0);
            }
        } else {
            float4 scl = ((const float4*)inscale)[c4];
            float4 sht = ((const float4*)inshift)[c4];
#pragma unroll
            for (int i = 0; i < 16; i++) {
                int m = r0 + 8 * i;
                int row = row0 + m;
                float4 v = make_float4(0.f, 0.f, 0.f, 0.f);
                if (row < M) v = ((const float4*)X)[(size_t)row * 16 + c4];
                v.x = v.x * scl.x + sht.x;
                v.y = v.y * scl.y + sht.y;
                v.z = v.z * scl.z + sht.z;
                v.w = v.w * scl.w + sht.w;
                int cs = (c4 ^ (m >> 3)) & 15;
                *(float4*)&Xs[m * 64 + cs * 4] = v;
            }
        }
    }
    cpasync_wait_all();
    __syncthreads();

    int tx = tid & 7;
    int ty = tid >> 3;

    unsigned long long acc[8][4];
#pragma unroll
    for (int r = 0; r < 8; r++)
#pragma unroll
        for (int j = 0; j < 4; j++) acc[r][j] = 0ull;

#pragma unroll
    for (int k4 = 0; k4 < 16; k4++) {
        float4 xv[8];
        int cs = (k4 ^ ty) & 15;
#pragma unroll
        for (int r = 0; r < 8; r++) {
            int m = ty * 8 + r;
            xv[r] = *(const float4*)&Xs[m * 64 + cs * 4];
        }
#pragma unroll
        for (int kk = 0; kk < 4; kk++) {
            int k = k4 * 4 + kk;
            ulonglong2 w0 = *(const ulonglong2*)&Ws[k * 64 + tx * 8];
            ulonglong2 w1 = *(const ulonglong2*)&Ws[k * 64 + tx * 8 + 4];
#pragma unroll
            for (int r = 0; r < 8; r++) {
                float xs = (kk == 0) ? xv[r].x
                         : (kk == 1) ? xv[r].y
                         : (kk == 2) ? xv[r].z : xv[r].w;
                unsigned long long xx = bcast2(xs);
                ffma2(acc[r][0], xx, w0.x);
                ffma2(acc[r][1], xx, w0.y);
                ffma2(acc[r][2], xx, w1.x);
                ffma2(acc[r][3], xx, w1.y);
            }
        }
    }

    float bv[8];
#pragma unroll
    for (int j = 0; j < 8; j++) bv[j] = 0.f;
    if (bias) {
        float4 b0 = ((const float4*)bias)[tx * 2];
        float4 b1 = ((const float4*)bias)[tx * 2 + 1];
        bv[0] = b0.x; bv[1] = b0.y; bv[2] = b0.z; bv[3] = b0.w;
        bv[4] = b1.x; bv[5] = b1.y; bv[6] = b1.z; bv[7] = b1.w;
    }
    float sv[8];
    if (seed) {
#pragma unroll
        for (int j = 0; j < 8; j++) sv[j] = seed[tx * 8 + j];
    }
    float s[8], q[8];
#pragma unroll
    for (int j = 0; j < 8; j++) { s[j] = 0.f; q[j] = 0.f; }

#pragma unroll
    for (int r = 0; r < 8; r++) {
        int row = row0 + ty * 8 + r;
        bool ok = row < M;
        float o[8];
#pragma unroll
        for (int j = 0; j < 4; j++) {
            float2 p = *(float2*)&acc[r][j];
            o[2 * j] = p.x + bv[2 * j];
            o[2 * j + 1] = p.y + bv[2 * j + 1];
        }
        if (relu) {
#pragma unroll
            for (int j = 0; j < 8; j++) o[j] = fmaxf(o[j], 0.f);
        }
        if (bnstat && ok) {
#pragma unroll
            for (int j = 0; j < 8; j++) {
                s[j] += o[j];
                q[j] += o[j] * o[j];
            }
        }
        if (seed) {
            float p = 0.f;
#pragma unroll
            for (int j = 0; j < 8; j++) p += o[j] * sv[j];
            p += __shfl_xor_sync(0xffffffffu, p, 1);
            if (ok && (tx & 1) == 0) scout[row * NH + (tx >> 1)] = p * 0.25f;
        }
        if (ok && Y) {
            ((float4*)Y)[(size_t)row * 16 + tx * 2] =
                make_float4(o[0], o[1], o[2], o[3]);
            ((float4*)Y)[(size_t)row * 16 + tx * 2 + 1] =
                make_float4(o[4], o[5], o[6], o[7]);
        }
    }

    if (bnstat) {
        __syncthreads();
        float* red = Xs;
#pragma unroll
        for (int j = 0; j < 8; j++) {
            int c = tx * 8 + j;
            red[c * 17 + ty] = s[j];
            red[64 * 17 + c * 17 + ty] = q[j];
        }
        __syncthreads();
        {
            int c = tid & 63;
            int which = tid >> 6;
            float t = 0.f;
#pragma unroll
            for (int i = 0; i < 16; i++) t += red[which * 64 * 17 + c * 17 + i];
            atomicAdd(&g_red[which * 64 + c], t);
        }
    }
}

// ---------------- attention readout: one block per graph ----------------
__global__ void k_attn() {
    int g = blockIdx.x;
    int tid = threadIdx.x;  // 128
    int beg = g_goff[g], end = g_goff[g + 1];
    __shared__ float shm[4 * 4];
    __shared__ float shs[4 * 4];
    __shared__ float mx[4], sm[4];
    __shared__ float pacc[64];

    float m0 = -1e30f, m1 = -1e30f, m2 = -1e30f, m3 = -1e30f;
    for (int n = beg + tid; n < end; n += 128) {
        float4 v = ((const float4*)g_sc)[n];
        m0 = fmaxf(m0, v.x); m1 = fmaxf(m1, v.y);
        m2 = fmaxf(m2, v.z); m3 = fmaxf(m3, v.w);
    }
#pragma unroll
    for (int o = 16; o; o >>= 1) {
        m0 = fmaxf(m0, __shfl_xor_sync(0xffffffffu, m0, o));
        m1 = fmaxf(m1, __shfl_xor_sync(0xffffffffu, m1, o));
        m2 = fmaxf(m2, __shfl_xor_sync(0xffffffffu, m2, o));
        m3 = fmaxf(m3, __shfl_xor_sync(0xffffffffu, m3, o));
    }
    if ((tid & 31) == 0) {
        int w = tid >> 5;
        shm[w * 4 + 0] = m0; shm[w * 4 + 1] = m1;
        shm[w * 4 + 2] = m2; shm[w * 4 + 3] = m3;
    }
    __syncthreads();
    if (tid < 4) {
        mx[tid] = fmaxf(fmaxf(shm[tid], shm[4 + tid]),
                        fmaxf(shm[8 + tid], shm[12 + tid]));
    }
    __syncthreads();

    float s0 = 0.f, s1 = 0.f, s2 = 0.f, s3 = 0.f;
    float q0 = mx[0], q1 = mx[1], q2 = mx[2], q3 = mx[3];
    for (int n = beg + tid; n < end; n += 128) {
        float4 v = ((const float4*)g_sc)[n];
        v.x = expf(v.x - q0); v.y = expf(v.y - q1);
        v.z = expf(v.z - q2); v.w = expf(v.w - q3);
        ((float4*)g_sc)[n] = v;
        s0 += v.x; s1 += v.y; s2 += v.z; s3 += v.w;
    }
#pragma unroll
    for (int o = 16; o; o >>= 1) {
        s0 += __shfl_xor_sync(0xffffffffu, s0, o);
        s1 += __shfl_xor_sync(0xffffffffu, s1, o);
        s2 += __shfl_xor_sync(0xffffffffu, s2, o);
        s3 += __shfl_xor_sync(0xffffffffu, s3, o);
    }
    if ((tid & 31) == 0) {
        int w = tid >> 5;
        shs[w * 4 + 0] = s0; shs[w * 4 + 1] = s1;
        shs[w * 4 + 2] = s2; shs[w * 4 + 3] = s3;
    }
    __syncthreads();
    if (tid < 4) {
        float t = shs[tid] + shs[4 + tid] + shs[8 + tid] + shs[12 + tid];
        sm[tid] = (t > 0.f) ? (1.f / t) : 0.f;
    }
    if (tid < 64) pacc[tid] = 0.f;
    __syncthreads();

    int c = tid & 63;
    int half = tid >> 6;
    int hh = c >> 4;
    float acc = 0.f;
    for (int n = beg + half; n < end; n += 2) {
        float w = g_sc[n * NH + hh];
        acc += w * g_agg[(size_t)n * HD + c];
    }
    if (half == 1) atomicAdd(&pacc[c], acc);
    __syncthreads();
    if (half == 0) g_pool[g * HD + c] = (acc + pacc[c]) * sm[hh];
}

__global__ void k_logits(const float* __restrict__ embed,
                         const float* __restrict__ W,
                         const float* __restrict__ b, float* __restrict__ out) {
    int g = blockIdx.x;
    int t = threadIdx.x;  // 128
    __shared__ float e[64];
    if (t < 64) e[t] = embed[g * 64 + t];
    __syncthreads();
    float s = b[t];
#pragma unroll
    for (int k = 0; k < 64; k++) s += e[k] * W[k * NO + t];
    out[g * NO + t] = s;
}

// ---------------- launch ----------------
extern "C" void kernel_launch(void* const* d_in, const int* in_sizes, int n_in,
                              void* d_out, int out_size) {
    const float* x = (const float*)d_in[0];
    const int* ei = (const int*)d_in[1];
    const int* batch = (const int*)d_in[2];
    const float* fng = (const float*)d_in[3];
    const float* fnb = (const float*)d_in[4];
    const float* projW = (const float*)d_in[5];
    const float* projb = (const float*)d_in[6];
    const float* mlpW = (const float*)d_in[7];
    const float* mlpb = (const float*)d_in[8];
    const float* ng = (const float*)d_in[9];
    const float* nb = (const float*)d_in[10];
    const float* seed = (const float*)d_in[11];
    const float* Wk = (const float*)d_in[12];
    const float* Wv = (const float*)d_in[13];
    const float* Wo = (const float*)d_in[14];
    const float* predW = (const float*)d_in[15];
    const float* predb = (const float*)d_in[16];
    float* out = (float*)d_out;

    float *h, *agg, *z, *pool, *bns, *bnt, *sc;
    cudaGetSymbolAddress((void**)&h, g_h);
    cudaGetSymbolAddress((void**)&agg, g_agg);
    cudaGetSymbolAddress((void**)&z, g_z);
    cudaGetSymbolAddress((void**)&pool, g_pool);
    cudaGetSymbolAddress((void**)&bns, g_bns);
    cudaGetSymbolAddress((void**)&bnt, g_bnt);
    cudaGetSymbolAddress((void**)&sc, g_sc);

    const int* src = ei;
    const int* dst = ei + NE;

    const int GB = (NN + 127) / 128;       // 782
    const int EW = (NN * 16 + 255) / 256;
    const int EB = (NE + 255) / 256;
    const int NB = (NN + 255) / 256;
    const int GTB = (NN * 16 + 255) / 256;
    const int NCHUNK = (NN + 1023) / 1024;

    // proj GEMM kept at launch index 3 for the profiler.
    k_bn_stats<<<256, 256>>>(x);
    k_deg_zero<<<NB, 256>>>();
    k_bn_finalize<<<1, 64>>>(fng, fnb, 0);
    gemm128<<<GB, 128>>>(x, projW, projb, h, NN, 1, bns, bnt, 0, nullptr,
                         nullptr);
    k_csr_count<<<EB, 256>>>(dst);
    k_scan_chunk<<<NCHUNK, 256>>>();
    k_scan_tops<<<1, 128>>>(NCHUNK);
    k_scan_final<<<NB, 256>>>();
    k_csr_fill<<<EB, 256>>>(src, dst);
    k_goff<<<NB, 256>>>(batch);

    for (int m = 0; m < 4; m++) {
        const float* Wm = mlpW + m * 3 * 4096;
        const float* bm = mlpb + m * 3 * 64;
        // c = 0: gather(h, plain) -> agg ; MLP agg->z->agg->z (+BN stats)
        k_gather<<<GTB, 256>>>(h, 0);
        gemm128<<<GB, 128>>>(agg, Wm, bm, z, NN, 1, nullptr, nullptr, 0,
                             nullptr, nullptr);
        gemm128<<<GB, 128>>>(z, Wm + 4096, bm + 64, agg, NN, 1, nullptr,
                             nullptr, 0, nullptr, nullptr);
        gemm128<<<GB, 128>>>(agg, Wm + 8192, bm + 128, z, NN, 0, nullptr,
                             nullptr, 1, nullptr, nullptr);
        k_bn_finalize<<<1, 64>>>(ng + m * 64, nb + m * 64, 0);
        // c = 1: gather(bnrelu(z), slot 0) -> agg ; MLP
        k_gather<<<GTB, 256>>>(z, 1);
        gemm128<<<GB, 128>>>(agg, Wm, bm, z, NN, 1, nullptr, nullptr, 0,
                             nullptr, nullptr);
        gemm128<<<GB, 128>>>(z, Wm + 4096, bm + 64, agg, NN, 1, nullptr,
                             nullptr, 0, nullptr, nullptr);
        gemm128<<<GB, 128>>>(agg, Wm + 8192, bm + 128, z, NN, 0, nullptr,
                             nullptr, 1, nullptr, nullptr);
        k_bn_finalize<<<1, 64>>>(ng + m * 64, nb + m * 64, 1);
        // h = relu(bn(z)) + h
        k_resid_fused<<<EW, 256>>>();
    }

    // attention: scores fused into Wk GEMM (K never materialized); V -> agg
    gemm128<<<GB, 128>>>(h, Wk, nullptr, nullptr, NN, 0, nullptr, nullptr, 0,
                         seed, sc);
    gemm128<<<GB, 128>>>(h, Wv, nullptr, agg, NN, 0, nullptr, nullptr, 0,
                         nullptr, nullptr);
    k_attn<<<NG, 128>>>();

    // embed = pooled @ Wo -> d_out[0 : NG*HD)
    gemm128<<<(NG + 127) / 128, 128>>>(pool, Wo, nullptr, out, NG, 0, nullptr,
                                       nullptr, 0, nullptr, nullptr);
    // logits -> d_out[NG*HD : ...)
    k_logits<<<NG, 128>>>(out, predW, predb, out + NG * HD);
}

// round 14
// speedup vs baseline: 1.0367x; 1.0367x over previous
#include <cuda_runtime.h>

#define NN 100000
#define NE 1000000
#define HD 64
#define NG 1000
#define NH 4
#define NO 128

// ---------------- scratch (device globals; no allocation) ----------------
// Working set kept at 3 big buffers (h, agg, z) = 76.8 MB so it stays
// L2-resident (126 MB) -- g_res was removed (res == h invariantly).
static __device__ float g_h[NN * HD];
static __device__ float g_agg[NN * HD];
static __device__ float g_z[NN * HD];
static __device__ float g_red[2 * HD];     // zero at entry; finalize re-zeroes
static __device__ float g_bns[2 * HD];     // BN scale, 2 slots
static __device__ float g_bnt[2 * HD];     // BN shift, 2 slots
static __device__ float g_sc[NN * NH];
static __device__ float g_pool[NG * HD];
// CSR scratch
static __device__ int g_deg[NN];
static __device__ int g_incl[NN];
static __device__ int g_off[NN + 1];
static __device__ int g_cur[NN];
static __device__ int g_bsum[128];
static __device__ int g_bpre[128];
static __device__ int g_esrc[NE];
static __device__ int g_goff[NG + 1];

// ---------------- f32x2 packed FMA helpers ----------------
__device__ __forceinline__ void ffma2(unsigned long long& d,
                                      unsigned long long a,
                                      unsigned long long b) {
    asm("fma.rn.f32x2 %0, %1, %2, %0;" : "+l"(d) : "l"(a), "l"(b));
}
__device__ __forceinline__ unsigned long long bcast2(float x) {
    unsigned long long r;
    asm("mov.b64 %0, {%1, %1};" : "=l"(r) : "f"(x));
    return r;
}

// ---------------- BatchNorm ----------------
__global__ void k_bn_stats(const float* __restrict__ Z) {
    int f = threadIdx.x & 63;
    int rl = threadIdx.x >> 6;  // 0..3
    float s = 0.f, q = 0.f;
    for (int r = blockIdx.x * 4 + rl; r < NN; r += gridDim.x * 4) {
        float v = Z[(size_t)r * HD + f];
        s += v;
        q += v * v;
    }
    __shared__ float sh[512];
    sh[threadIdx.x] = s;
    sh[256 + threadIdx.x] = q;
    __syncthreads();
    if (rl == 0) {
        s = sh[f] + sh[64 + f] + sh[128 + f] + sh[192 + f];
        q = sh[256 + f] + sh[320 + f] + sh[384 + f] + sh[448 + f];
        atomicAdd(&g_red[f], s);
        atomicAdd(&g_red[64 + f], q);
    }
}

// computes BN scale/shift into slot, then zeroes g_red (keeps invariant)
__global__ void k_bn_finalize(const float* __restrict__ gamma,
                              const float* __restrict__ beta, int slot) {
    int f = threadIdx.x;  // 64 threads
    float inv_n = 1.f / (float)NN;
    float mu = g_red[f] * inv_n;
    float var = fmaxf(g_red[64 + f] * inv_n - mu * mu, 0.f);
    float rs = rsqrtf(var + 1e-5f);
    float sc = rs * gamma[f];
    g_bns[slot * 64 + f] = sc;
    g_bnt[slot * 64 + f] = beta[f] - mu * sc;
    g_red[f] = 0.f;
    g_red[64 + f] = 0.f;
}

// h = relu(z*s1+t1) + h   (slot 1; res == h invariant, so no res buffer)
__global__ void k_resid_fused() {
    int t = blockIdx.x * blockDim.x + threadIdx.x;
    if (t >= NN * 16) return;
    int c4 = t & 15;
    float4 s = ((const float4*)(g_bns + 64))[c4];
    float4 b = ((const float4*)(g_bnt + 64))[c4];
    float4 v = ((const float4*)g_z)[t];
    float4 r = ((const float4*)g_h)[t];
    float4 a;
    a.x = fmaxf(v.x * s.x + b.x, 0.f) + r.x;
    a.y = fmaxf(v.y * s.y + b.y, 0.f) + r.y;
    a.z = fmaxf(v.z * s.z + b.z, 0.f) + r.z;
    a.w = fmaxf(v.w * s.w + b.w, 0.f) + r.w;
    ((float4*)g_h)[t] = a;
}

// ---------------- CSR build ----------------
__global__ void k_deg_zero() {
    int i = blockIdx.x * blockDim.x + threadIdx.x;
    if (i < NN) g_deg[i] = 0;
}

__global__ void k_csr_count(const int* __restrict__ dst) {
    int e = blockIdx.x * blockDim.x + threadIdx.x;
    if (e < NE) atomicAdd(&g_deg[dst[e]], 1);
}

__global__ void k_scan_chunk() {
    __shared__ int ssum[256];
    int blk = blockIdx.x;
    int base = blk * 1024;
    int tid = threadIdx.x;
    int v[4];
    int s = 0;
#pragma unroll
    for (int j = 0; j < 4; j++) {
        int idx = base + tid * 4 + j;
        int d = (idx < NN) ? g_deg[idx] : 0;
        v[j] = d;
        s += d;
    }
    ssum[tid] = s;
    __syncthreads();
    for (int o = 1; o < 256; o <<= 1) {
        int x = (tid >= o) ? ssum[tid - o] : 0;
        __syncthreads();
        ssum[tid] += x;
        __syncthreads();
    }
    int run = ssum[tid] - s;
#pragma unroll
    for (int j = 0; j < 4; j++) {
        run += v[j];
        int idx = base + tid * 4 + j;
        if (idx < NN) g_incl[idx] = run;
    }
    if (tid == 255) g_bsum[blk] = ssum[255];
}

__global__ void k_scan_tops(int nchunks) {
    __shared__ int sh[128];
    int tid = threadIdx.x;
    int v = (tid < nchunks) ? g_bsum[tid] : 0;
    sh[tid] = v;
    __syncthreads();
    for (int o = 1; o < 128; o <<= 1) {
        int x = (tid >= o) ? sh[tid - o] : 0;
        __syncthreads();
        sh[tid] += x;
        __syncthreads();
    }
    g_bpre[tid] = sh[tid] - v;
}

__global__ void k_scan_final() {
    int i = blockIdx.x * blockDim.x + threadIdx.x;
    if (i == 0) g_off[0] = 0;
    if (i < NN) {
        int off_ip1 = g_incl[i] + g_bpre[i >> 10];
        g_off[i + 1] = off_ip1;
        int off_i = (i == 0) ? 0 : (g_incl[i - 1] + g_bpre[(i - 1) >> 10]);
        g_cur[i] = off_i;
    }
}

__global__ void k_csr_fill(const int* __restrict__ src,
                           const int* __restrict__ dst) {
    int e = blockIdx.x * blockDim.x + threadIdx.x;
    if (e >= NE) return;
    int d = dst[e];
    int pos = atomicAdd(&g_cur[d], 1);
    g_esrc[pos] = src[e];
}

__global__ void k_goff(const int* __restrict__ batch) {
    int i = blockIdx.x * blockDim.x + threadIdx.x;
    if (i >= NN) return;
    int b = batch[i];
    if (i == 0) {
        for (int g = 0; g <= b; g++) g_goff[g] = 0;
    } else {
        int p = batch[i - 1];
        for (int g = p + 1; g <= b; g++) g_goff[g] = i;
    }
    if (i == NN - 1) {
        for (int g = b + 1; g <= NG; g++) g_goff[g] = NN;
    }
}

// ---- gather: agg[n] = f(X[n]) + sum f(X[src]); f = affine+relu if aff ----
__device__ __forceinline__ float4 xf4(float4 v, float4 s, float4 b, int aff) {
    if (!aff) return v;
    float4 o;
    o.x = fmaxf(v.x * s.x + b.x, 0.f);
    o.y = fmaxf(v.y * s.y + b.y, 0.f);
    o.z = fmaxf(v.z * s.z + b.z, 0.f);
    o.w = fmaxf(v.w * s.w + b.w, 0.f);
    return o;
}

__global__ void k_gather(const float* __restrict__ X, int aff) {
    int t = blockIdx.x * blockDim.x + threadIdx.x;
    int n = t >> 4;
    if (n >= NN) return;
    int l = t & 15;
    float4 s = make_float4(1.f, 1.f, 1.f, 1.f);
    float4 b = make_float4(0.f, 0.f, 0.f, 0.f);
    if (aff) {  // slot 0
        s = ((const float4*)g_bns)[l];
        b = ((const float4*)g_bnt)[l];
    }
    int beg = g_off[n], end = g_off[n + 1];
    float4 acc = xf4(((const float4*)X)[(size_t)n * 16 + l], s, b, aff);
    int e = beg;
    for (; e + 4 <= end; e += 4) {
        int s0 = __ldg(&g_esrc[e + 0]);
        int s1 = __ldg(&g_esrc[e + 1]);
        int s2 = __ldg(&g_esrc[e + 2]);
        int s3 = __ldg(&g_esrc[e + 3]);
        float4 v0 = ((const float4*)X)[(size_t)s0 * 16 + l];
        float4 v1 = ((const float4*)X)[(size_t)s1 * 16 + l];
        float4 v2 = ((const float4*)X)[(size_t)s2 * 16 + l];
        float4 v3 = ((const float4*)X)[(size_t)s3 * 16 + l];
        v0 = xf4(v0, s, b, aff);
        v1 = xf4(v1, s, b, aff);
        v2 = xf4(v2, s, b, aff);
        v3 = xf4(v3, s, b, aff);
        acc.x += v0.x + v1.x + v2.x + v3.x;
        acc.y += v0.y + v1.y + v2.y + v3.y;
        acc.z += v0.z + v1.z + v2.z + v3.z;
        acc.w += v0.w + v1.w + v2.w + v3.w;
    }
    for (; e < end; e++) {
        int si = __ldg(&g_esrc[e]);
        float4 v = xf4(((const float4*)X)[(size_t)si * 16 + l], s, b, aff);
        acc.x += v.x; acc.y += v.y; acc.z += v.z; acc.w += v.w;
    }
    ((float4*)g_agg)[(size_t)n * 16 + l] = acc;
}

// ---------------- GEMM: Y = op(X) @ W + b ----------------
// 128-row tile x 64 cols, 128 threads, 8x8 micro-tile, packed f32x2 FMA.
// Options: input affine (BN fold), relu, fused BN stats,
// fused attention score (seed != null: write scout instead of Y).
__global__ void __launch_bounds__(128, 4)
gemm128(const float* __restrict__ X, const float* __restrict__ W,
        const float* __restrict__ bias, float* __restrict__ Y, int M, int relu,
        const float* __restrict__ inscale, const float* __restrict__ inshift,
        int bnstat, const float* __restrict__ seed, float* __restrict__ scout) {
    __shared__ float Ws[64 * 64];
    __shared__ float Xs[128 * 64];
    int tid = threadIdx.x;
    int row0 = blockIdx.x << 7;

    {
        const float4* W4 = (const float4*)W;
        float4* Ws4 = (float4*)Ws;
#pragma unroll
        for (int i = 0; i < 8; i++) Ws4[tid + 128 * i] = W4[tid + 128 * i];
    }
    {
        int c4 = tid & 15;
        int r0 = tid >> 4;
        float4 scl = make_float4(1.f, 1.f, 1.f, 1.f);
        float4 sht = make_float4(0.f, 0.f, 0.f, 0.f);
        if (inscale) {
            scl = ((const float4*)inscale)[c4];
            sht = ((const float4*)inshift)[c4];
        }
#pragma unroll
        for (int i = 0; i < 16; i++) {
            int m = r0 + 8 * i;
            int row = row0 + m;
            float4 v = make_float4(0.f, 0.f, 0.f, 0.f);
            if (row < M) v = ((const float4*)X)[(size_t)row * 16 + c4];
            v.x = v.x * scl.x + sht.x;
            v.y = v.y * scl.y + sht.y;
            v.z = v.z * scl.z + sht.z;
            v.w = v.w * scl.w + sht.w;
            int cs = (c4 ^ (m >> 3)) & 15;
            *(float4*)&Xs[m * 64 + cs * 4] = v;
        }
    }
    __syncthreads();

    int tx = tid & 7;
    int ty = tid >> 3;

    unsigned long long acc[8][4];
#pragma unroll
    for (int r = 0; r < 8; r++)
#pragma unroll
        for (int j = 0; j < 4; j++) acc[r][j] = 0ull;

#pragma unroll
    for (int k4 = 0; k4 < 16; k4++) {
        float4 xv[8];
        int cs = (k4 ^ ty) & 15;
#pragma unroll
        for (int r = 0; r < 8; r++) {
            int m = ty * 8 + r;
            xv[r] = *(const float4*)&Xs[m * 64 + cs * 4];
        }
#pragma unroll
        for (int kk = 0; kk < 4; kk++) {
            int k = k4 * 4 + kk;
            ulonglong2 w0 = *(const ulonglong2*)&Ws[k * 64 + tx * 8];
            ulonglong2 w1 = *(const ulonglong2*)&Ws[k * 64 + tx * 8 + 4];
#pragma unroll
            for (int r = 0; r < 8; r++) {
                float xs = (kk == 0) ? xv[r].x
                         : (kk == 1) ? xv[r].y
                         : (kk == 2) ? xv[r].z : xv[r].w;
                unsigned long long xx = bcast2(xs);
                ffma2(acc[r][0], xx, w0.x);
                ffma2(acc[r][1], xx, w0.y);
                ffma2(acc[r][2], xx, w1.x);
                ffma2(acc[r][3], xx, w1.y);
            }
        }
    }

    float bv[8];
#pragma unroll
    for (int j = 0; j < 8; j++) bv[j] = 0.f;
    if (bias) {
        float4 b0 = ((const float4*)bias)[tx * 2];
        float4 b1 = ((const float4*)bias)[tx * 2 + 1];
        bv[0] = b0.x; bv[1] = b0.y; bv[2] = b0.z; bv[3] = b0.w;
        bv[4] = b1.x; bv[5] = b1.y; bv[6] = b1.z; bv[7] = b1.w;
    }
    float sv[8];
    if (seed) {
#pragma unroll
        for (int j = 0; j < 8; j++) sv[j] = seed[tx * 8 + j];
    }
    float s[8], q[8];
#pragma unroll
    for (int j = 0; j < 8; j++) { s[j] = 0.f; q[j] = 0.f; }

#pragma unroll
    for (int r = 0; r < 8; r++) {
        int row = row0 + ty * 8 + r;
        bool ok = row < M;
        float o[8];
#pragma unroll
        for (int j = 0; j < 4; j++) {
            float2 p = *(float2*)&acc[r][j];
            o[2 * j] = p.x + bv[2 * j];
            o[2 * j + 1] = p.y + bv[2 * j + 1];
        }
        if (relu) {
#pragma unroll
            for (int j = 0; j < 8; j++) o[j] = fmaxf(o[j], 0.f);
        }
        if (bnstat && ok) {
#pragma unroll
            for (int j = 0; j < 8; j++) {
                s[j] += o[j];
                q[j] += o[j] * o[j];
            }
        }
        if (seed) {
            float p = 0.f;
#pragma unroll
            for (int j = 0; j < 8; j++) p += o[j] * sv[j];
            p += __shfl_xor_sync(0xffffffffu, p, 1);
            if (ok && (tx & 1) == 0) scout[row * NH + (tx >> 1)] = p * 0.25f;
        }
        if (ok && Y) {
            ((float4*)Y)[(size_t)row * 16 + tx * 2] =
                make_float4(o[0], o[1], o[2], o[3]);
            ((float4*)Y)[(size_t)row * 16 + tx * 2 + 1] =
                make_float4(o[4], o[5], o[6], o[7]);
        }
    }

    if (bnstat) {
        __syncthreads();
        float* red = Xs;
#pragma unroll
        for (int j = 0; j < 8; j++) {
            int c = tx * 8 + j;
            red[c * 17 + ty] = s[j];
            red[64 * 17 + c * 17 + ty] = q[j];
        }
        __syncthreads();
        {
            int c = tid & 63;
            int which = tid >> 6;
            float t = 0.f;
#pragma unroll
            for (int i = 0; i < 16; i++) t += red[which * 64 * 17 + c * 17 + i];
            atomicAdd(&g_red[which * 64 + c], t);
        }
    }
}

// ---------------- attention readout: one block per graph ----------------
__global__ void k_attn() {
    int g = blockIdx.x;
    int tid = threadIdx.x;  // 128
    int beg = g_goff[g], end = g_goff[g + 1];
    __shared__ float shm[4 * 4];
    __shared__ float shs[4 * 4];
    __shared__ float mx[4], sm[4];
    __shared__ float pacc[64];

    float m0 = -1e30f, m1 = -1e30f, m2 = -1e30f, m3 = -1e30f;
    for (int n = beg + tid; n < end; n += 128) {
        float4 v = ((const float4*)g_sc)[n];
        m0 = fmaxf(m0, v.x); m1 = fmaxf(m1, v.y);
        m2 = fmaxf(m2, v.z); m3 = fmaxf(m3, v.w);
    }
#pragma unroll
    for (int o = 16; o; o >>= 1) {
        m0 = fmaxf(m0, __shfl_xor_sync(0xffffffffu, m0, o));
        m1 = fmaxf(m1, __shfl_xor_sync(0xffffffffu, m1, o));
        m2 = fmaxf(m2, __shfl_xor_sync(0xffffffffu, m2, o));
        m3 = fmaxf(m3, __shfl_xor_sync(0xffffffffu, m3, o));
    }
    if ((tid & 31) == 0) {
        int w = tid >> 5;
        shm[w * 4 + 0] = m0; shm[w * 4 + 1] = m1;
        shm[w * 4 + 2] = m2; shm[w * 4 + 3] = m3;
    }
    __syncthreads();
    if (tid < 4) {
        mx[tid] = fmaxf(fmaxf(shm[tid], shm[4 + tid]),
                        fmaxf(shm[8 + tid], shm[12 + tid]));
    }
    __syncthreads();

    float s0 = 0.f, s1 = 0.f, s2 = 0.f, s3 = 0.f;
    float q0 = mx[0], q1 = mx[1], q2 = mx[2], q3 = mx[3];
    for (int n = beg + tid; n < end; n += 128) {
        float4 v = ((const float4*)g_sc)[n];
        v.x = expf(v.x - q0); v.y = expf(v.y - q1);
        v.z = expf(v.z - q2); v.w = expf(v.w - q3);
        ((float4*)g_sc)[n] = v;
        s0 += v.x; s1 += v.y; s2 += v.z; s3 += v.w;
    }
#pragma unroll
    for (int o = 16; o; o >>= 1) {
        s0 += __shfl_xor_sync(0xffffffffu, s0, o);
        s1 += __shfl_xor_sync(0xffffffffu, s1, o);
        s2 += __shfl_xor_sync(0xffffffffu, s2, o);
        s3 += __shfl_xor_sync(0xffffffffu, s3, o);
    }
    if ((tid & 31) == 0) {
        int w = tid >> 5;
        shs[w * 4 + 0] = s0; shs[w * 4 + 1] = s1;
        shs[w * 4 + 2] = s2; shs[w * 4 + 3] = s3;
    }
    __syncthreads();
    if (tid < 4) {
        float t = shs[tid] + shs[4 + tid] + shs[8 + tid] + shs[12 + tid];
        sm[tid] = (t > 0.f) ? (1.f / t) : 0.f;
    }
    if (tid < 64) pacc[tid] = 0.f;
    __syncthreads();

    int c = tid & 63;
    int half = tid >> 6;
    int hh = c >> 4;
    float acc = 0.f;
    for (int n = beg + half; n < end; n += 2) {
        float w = g_sc[n * NH + hh];
        acc += w * g_agg[(size_t)n * HD + c];
    }
    if (half == 1) atomicAdd(&pacc[c], acc);
    __syncthreads();
    if (half == 0) g_pool[g * HD + c] = (acc + pacc[c]) * sm[hh];
}

__global__ void k_logits(const float* __restrict__ embed,
                         const float* __restrict__ W,
                         const float* __restrict__ b, float* __restrict__ out) {
    int g = blockIdx.x;
    int t = threadIdx.x;  // 128
    __shared__ float e[64];
    if (t < 64) e[t] = embed[g * 64 + t];
    __syncthreads();
    float s = b[t];
#pragma unroll
    for (int k = 0; k < 64; k++) s += e[k] * W[k * NO + t];
    out[g * NO + t] = s;
}

// ---------------- launch ----------------
extern "C" void kernel_launch(void* const* d_in, const int* in_sizes, int n_in,
                              void* d_out, int out_size) {
    const float* x = (const float*)d_in[0];
    const int* ei = (const int*)d_in[1];
    const int* batch = (const int*)d_in[2];
    const float* fng = (const float*)d_in[3];
    const float* fnb = (const float*)d_in[4];
    const float* projW = (const float*)d_in[5];
    const float* projb = (const float*)d_in[6];
    const float* mlpW = (const float*)d_in[7];
    const float* mlpb = (const float*)d_in[8];
    const float* ng = (const float*)d_in[9];
    const float* nb = (const float*)d_in[10];
    const float* seed = (const float*)d_in[11];
    const float* Wk = (const float*)d_in[12];
    const float* Wv = (const float*)d_in[13];
    const float* Wo = (const float*)d_in[14];
    const float* predW = (const float*)d_in[15];
    const float* predb = (const float*)d_in[16];
    float* out = (float*)d_out;

    float *h, *agg, *z, *pool, *bns, *bnt, *sc;
    cudaGetSymbolAddress((void**)&h, g_h);
    cudaGetSymbolAddress((void**)&agg, g_agg);
    cudaGetSymbolAddress((void**)&z, g_z);
    cudaGetSymbolAddress((void**)&pool, g_pool);
    cudaGetSymbolAddress((void**)&bns, g_bns);
    cudaGetSymbolAddress((void**)&bnt, g_bnt);
    cudaGetSymbolAddress((void**)&sc, g_sc);

    const int* src = ei;
    const int* dst = ei + NE;

    const int GB = (NN + 127) / 128;       // 782
    const int EW = (NN * 16 + 255) / 256;
    const int EB = (NE + 255) / 256;
    const int NB = (NN + 255) / 256;
    const int GTB = (NN * 16 + 255) / 256;
    const int NCHUNK = (NN + 1023) / 1024;

    // proj GEMM kept at launch index 3 for the profiler.
    k_bn_stats<<<256, 256>>>(x);
    k_deg_zero<<<NB, 256>>>();
    k_bn_finalize<<<1, 64>>>(fng, fnb, 0);
    gemm128<<<GB, 128>>>(x, projW, projb, h, NN, 1, bns, bnt, 0, nullptr,
                         nullptr);
    k_csr_count<<<EB, 256>>>(dst);
    k_scan_chunk<<<NCHUNK, 256>>>();
    k_scan_tops<<<1, 128>>>(NCHUNK);
    k_scan_final<<<NB, 256>>>();
    k_csr_fill<<<EB, 256>>>(src, dst);
    k_goff<<<NB, 256>>>(batch);

    for (int m = 0; m < 4; m++) {
        const float* Wm = mlpW + m * 3 * 4096;
        const float* bm = mlpb + m * 3 * 64;
        // c = 0: gather(h, plain) -> agg ; MLP agg->z->agg->z (+BN stats)
        k_gather<<<GTB, 256>>>(h, 0);
        gemm128<<<GB, 128>>>(agg, Wm, bm, z, NN, 1, nullptr, nullptr, 0,
                             nullptr, nullptr);
        gemm128<<<GB, 128>>>(z, Wm + 4096, bm + 64, agg, NN, 1, nullptr,
                             nullptr, 0, nullptr, nullptr);
        gemm128<<<GB, 128>>>(agg, Wm + 8192, bm + 128, z, NN, 0, nullptr,
                             nullptr, 1, nullptr, nullptr);
        k_bn_finalize<<<1, 64>>>(ng + m * 64, nb + m * 64, 0);
        // c = 1: gather(bnrelu(z), slot 0) -> agg ; MLP
        k_gather<<<GTB, 256>>>(z, 1);
        gemm128<<<GB, 128>>>(agg, Wm, bm, z, NN, 1, nullptr, nullptr, 0,
                             nullptr, nullptr);
        gemm128<<<GB, 128>>>(z, Wm + 4096, bm + 64, agg, NN, 1, nullptr,
                             nullptr, 0, nullptr, nullptr);
        gemm128<<<GB, 128>>>(agg, Wm + 8192, bm + 128, z, NN, 0, nullptr,
                             nullptr, 1, nullptr, nullptr);
        k_bn_finalize<<<1, 64>>>(ng + m * 64, nb + m * 64, 1);
        // h = relu(bn(z)) + h
        k_resid_fused<<<EW, 256>>>();
    }

    // attention: scores fused into Wk GEMM (K never materialized); V -> agg
    gemm128<<<GB, 128>>>(h, Wk, nullptr, nullptr, NN, 0, nullptr, nullptr, 0,
                         seed, sc);
    gemm128<<<GB, 128>>>(h, Wv, nullptr, agg, NN, 0, nullptr, nullptr, 0,
                         nullptr, nullptr);
    k_attn<<<NG, 128>>>();

    // embed = pooled @ Wo -> d_out[0 : NG*HD)
    gemm128<<<(NG + 127) / 128, 128>>>(pool, Wo, nullptr, out, NG, 0, nullptr,
                                       nullptr, 0, nullptr, nullptr);
    // logits -> d_out[NG*HD : ...)
    k_logits<<<NG, 128>>>(out, predW, predb, out + NG * HD);
}

// round 15
// speedup vs baseline: 1.0985x; 1.0596x over previous
#include <cuda_runtime.h>

#define NN 100000
#define NE 1000000
#define HD 64
#define NG 1000
#define NH 4
#define NO 128

// ---------------- scratch (device globals; no allocation) ----------------
static __device__ float g_h[NN * HD];
static __device__ float g_agg[NN * HD];
static __device__ float g_z[NN * HD];
static __device__ float g_red[2 * HD];     // zero at entry; finalize re-zeroes
static __device__ float g_bns[2 * HD];     // BN scale, 2 slots
static __device__ float g_bnt[2 * HD];     // BN shift, 2 slots
static __device__ float g_sc[NN * NH];
static __device__ float g_pool[NG * HD];
// CSR scratch
static __device__ int g_deg[NN];
static __device__ int g_incl[NN];
static __device__ int g_off[NN + 1];
static __device__ int g_cur[NN];
static __device__ int g_bsum[128];
static __device__ int g_bpre[128];
static __device__ int g_esrc[NE];
static __device__ int g_goff[NG + 1];

// ---------------- f32x2 packed FMA helpers ----------------
__device__ __forceinline__ void ffma2(unsigned long long& d,
                                      unsigned long long a,
                                      unsigned long long b) {
    asm("fma.rn.f32x2 %0, %1, %2, %0;" : "+l"(d) : "l"(a), "l"(b));
}
__device__ __forceinline__ unsigned long long bcast2(float x) {
    unsigned long long r;
    asm("mov.b64 %0, {%1, %1};" : "=l"(r) : "f"(x));
    return r;
}

// ---------------- BatchNorm ----------------
__global__ void k_bn_stats(const float* __restrict__ Z) {
    int f = threadIdx.x & 63;
    int rl = threadIdx.x >> 6;
    float s = 0.f, q = 0.f;
    for (int r = blockIdx.x * 4 + rl; r < NN; r += gridDim.x * 4) {
        float v = Z[(size_t)r * HD + f];
        s += v;
        q += v * v;
    }
    __shared__ float sh[512];
    sh[threadIdx.x] = s;
    sh[256 + threadIdx.x] = q;
    __syncthreads();
    if (rl == 0) {
        s = sh[f] + sh[64 + f] + sh[128 + f] + sh[192 + f];
        q = sh[256 + f] + sh[320 + f] + sh[384 + f] + sh[448 + f];
        atomicAdd(&g_red[f], s);
        atomicAdd(&g_red[64 + f], q);
    }
}

__global__ void k_bn_finalize(const float* __restrict__ gamma,
                              const float* __restrict__ beta, int slot) {
    int f = threadIdx.x;  // 64 threads
    float inv_n = 1.f / (float)NN;
    float mu = g_red[f] * inv_n;
    float var = fmaxf(g_red[64 + f] * inv_n - mu * mu, 0.f);
    float rs = rsqrtf(var + 1e-5f);
    float sc = rs * gamma[f];
    g_bns[slot * 64 + f] = sc;
    g_bnt[slot * 64 + f] = beta[f] - mu * sc;
    g_red[f] = 0.f;
    g_red[64 + f] = 0.f;
}

// h = relu(z*s1+t1) + h   (slot 1; res == h invariant)
__global__ void k_resid_fused() {
    int t = blockIdx.x * blockDim.x + threadIdx.x;
    if (t >= NN * 16) return;
    int c4 = t & 15;
    float4 s = ((const float4*)(g_bns + 64))[c4];
    float4 b = ((const float4*)(g_bnt + 64))[c4];
    float4 v = ((const float4*)g_z)[t];
    float4 r = ((const float4*)g_h)[t];
    float4 a;
    a.x = fmaxf(v.x * s.x + b.x, 0.f) + r.x;
    a.y = fmaxf(v.y * s.y + b.y, 0.f) + r.y;
    a.z = fmaxf(v.z * s.z + b.z, 0.f) + r.z;
    a.w = fmaxf(v.w * s.w + b.w, 0.f) + r.w;
    ((float4*)g_h)[t] = a;
}

// ---------------- CSR build ----------------
__global__ void k_deg_zero() {
    int i = blockIdx.x * blockDim.x + threadIdx.x;
    if (i < NN) g_deg[i] = 0;
}

__global__ void k_csr_count(const int* __restrict__ dst) {
    int e = blockIdx.x * blockDim.x + threadIdx.x;
    if (e < NE) atomicAdd(&g_deg[dst[e]], 1);
}

__global__ void k_scan_chunk() {
    __shared__ int ssum[256];
    int blk = blockIdx.x;
    int base = blk * 1024;
    int tid = threadIdx.x;
    int v[4];
    int s = 0;
#pragma unroll
    for (int j = 0; j < 4; j++) {
        int idx = base + tid * 4 + j;
        int d = (idx < NN) ? g_deg[idx] : 0;
        v[j] = d;
        s += d;
    }
    ssum[tid] = s;
    __syncthreads();
    for (int o = 1; o < 256; o <<= 1) {
        int x = (tid >= o) ? ssum[tid - o] : 0;
        __syncthreads();
        ssum[tid] += x;
        __syncthreads();
    }
    int run = ssum[tid] - s;
#pragma unroll
    for (int j = 0; j < 4; j++) {
        run += v[j];
        int idx = base + tid * 4 + j;
        if (idx < NN) g_incl[idx] = run;
    }
    if (tid == 255) g_bsum[blk] = ssum[255];
}

__global__ void k_scan_tops(int nchunks) {
    __shared__ int sh[128];
    int tid = threadIdx.x;
    int v = (tid < nchunks) ? g_bsum[tid] : 0;
    sh[tid] = v;
    __syncthreads();
    for (int o = 1; o < 128; o <<= 1) {
        int x = (tid >= o) ? sh[tid - o] : 0;
        __syncthreads();
        sh[tid] += x;
        __syncthreads();
    }
    g_bpre[tid] = sh[tid] - v;
}

__global__ void k_scan_final() {
    int i = blockIdx.x * blockDim.x + threadIdx.x;
    if (i == 0) g_off[0] = 0;
    if (i < NN) {
        int off_ip1 = g_incl[i] + g_bpre[i >> 10];
        g_off[i + 1] = off_ip1;
        int off_i = (i == 0) ? 0 : (g_incl[i - 1] + g_bpre[(i - 1) >> 10]);
        g_cur[i] = off_i;
    }
}

__global__ void k_csr_fill(const int* __restrict__ src,
                           const int* __restrict__ dst) {
    int e = blockIdx.x * blockDim.x + threadIdx.x;
    if (e >= NE) return;
    int d = dst[e];
    int pos = atomicAdd(&g_cur[d], 1);
    g_esrc[pos] = src[e];
}

__global__ void k_goff(const int* __restrict__ batch) {
    int i = blockIdx.x * blockDim.x + threadIdx.x;
    if (i >= NN) return;
    int b = batch[i];
    if (i == 0) {
        for (int g = 0; g <= b; g++) g_goff[g] = 0;
    } else {
        int p = batch[i - 1];
        for (int g = p + 1; g <= b; g++) g_goff[g] = i;
    }
    if (i == NN - 1) {
        for (int g = b + 1; g <= NG; g++) g_goff[g] = NN;
    }
}

// ---- gather: agg[n] = f(X[n]) + sum f(X[src]); f = affine+relu if aff ----
__device__ __forceinline__ float4 xf4(float4 v, float4 s, float4 b, int aff) {
    if (!aff) return v;
    float4 o;
    o.x = fmaxf(v.x * s.x + b.x, 0.f);
    o.y = fmaxf(v.y * s.y + b.y, 0.f);
    o.z = fmaxf(v.z * s.z + b.z, 0.f);
    o.w = fmaxf(v.w * s.w + b.w, 0.f);
    return o;
}

__global__ void k_gather(const float* __restrict__ X, int aff) {
    int t = blockIdx.x * blockDim.x + threadIdx.x;
    int n = t >> 4;
    if (n >= NN) return;
    int l = t & 15;
    float4 s = make_float4(1.f, 1.f, 1.f, 1.f);
    float4 b = make_float4(0.f, 0.f, 0.f, 0.f);
    if (aff) {  // slot 0
        s = ((const float4*)g_bns)[l];
        b = ((const float4*)g_bnt)[l];
    }
    int beg = g_off[n], end = g_off[n + 1];
    float4 acc = xf4(((const float4*)X)[(size_t)n * 16 + l], s, b, aff);
    int e = beg;
    for (; e + 4 <= end; e += 4) {
        int s0 = __ldg(&g_esrc[e + 0]);
        int s1 = __ldg(&g_esrc[e + 1]);
        int s2 = __ldg(&g_esrc[e + 2]);
        int s3 = __ldg(&g_esrc[e + 3]);
        float4 v0 = ((const float4*)X)[(size_t)s0 * 16 + l];
        float4 v1 = ((const float4*)X)[(size_t)s1 * 16 + l];
        float4 v2 = ((const float4*)X)[(size_t)s2 * 16 + l];
        float4 v3 = ((const float4*)X)[(size_t)s3 * 16 + l];
        v0 = xf4(v0, s, b, aff);
        v1 = xf4(v1, s, b, aff);
        v2 = xf4(v2, s, b, aff);
        v3 = xf4(v3, s, b, aff);
        acc.x += v0.x + v1.x + v2.x + v3.x;
        acc.y += v0.y + v1.y + v2.y + v3.y;
        acc.z += v0.z + v1.z + v2.z + v3.z;
        acc.w += v0.w + v1.w + v2.w + v3.w;
    }
    for (; e < end; e++) {
        int si = __ldg(&g_esrc[e]);
        float4 v = xf4(((const float4*)X)[(size_t)si * 16 + l], s, b, aff);
        acc.x += v.x; acc.y += v.y; acc.z += v.z; acc.w += v.w;
    }
    ((float4*)g_agg)[(size_t)n * 16 + l] = acc;
}

// ================= fused 3-GEMM MLP (8x8 micro-tile, 128 threads) ========
// Z = L3(relu(L2(relu(L1(X))))) + BN stats. Intermediates live in Xs.
// Key invariant: Xs row m is read AND written only by the 8 threads with
// ty == m>>3 (same warp) -> inter-phase Xs writeback needs no block sync;
// only the Ws reload does.
__global__ void __launch_bounds__(128, 4)
k_mlp3(const float* __restrict__ X, const float* __restrict__ W3,
       const float* __restrict__ b3, float* __restrict__ Z) {
    __shared__ float Ws[64 * 64];
    __shared__ float Xs[128 * 64];
    int tid = threadIdx.x;
    int row0 = blockIdx.x << 7;
    int tx = tid & 7;
    int ty = tid >> 3;

    // initial loads: W phase 0 + X tile (swizzle key m>>3, same as gemm128)
    {
        const float4* W4 = (const float4*)W3;
        float4* Ws4 = (float4*)Ws;
#pragma unroll
        for (int i = 0; i < 8; i++) Ws4[tid + 128 * i] = W4[tid + 128 * i];
    }
    {
        int c4 = tid & 15;
        int r0 = tid >> 4;
#pragma unroll
        for (int i = 0; i < 16; i++) {
            int m = r0 + 8 * i;
            int row = row0 + m;
            float4 v = make_float4(0.f, 0.f, 0.f, 0.f);
            if (row < NN) v = ((const float4*)X)[(size_t)row * 16 + c4];
            int cs = (c4 ^ (m >> 3)) & 15;
            *(float4*)&Xs[m * 64 + cs * 4] = v;
        }
    }
    __syncthreads();

    unsigned long long acc[8][4];

#pragma unroll 1
    for (int ph = 0; ph < 3; ph++) {
#pragma unroll
        for (int r = 0; r < 8; r++)
#pragma unroll
            for (int j = 0; j < 4; j++) acc[r][j] = 0ull;

        // ---- mainloop (identical to gemm128) ----
#pragma unroll
        for (int k4 = 0; k4 < 16; k4++) {
            float4 xv[8];
            int cs = (k4 ^ ty) & 15;
#pragma unroll
            for (int r = 0; r < 8; r++) {
                int m = ty * 8 + r;
                xv[r] = *(const float4*)&Xs[m * 64 + cs * 4];
            }
#pragma unroll
            for (int kk = 0; kk < 4; kk++) {
                int k = k4 * 4 + kk;
                ulonglong2 w0 = *(const ulonglong2*)&Ws[k * 64 + tx * 8];
                ulonglong2 w1 = *(const ulonglong2*)&Ws[k * 64 + tx * 8 + 4];
#pragma unroll
                for (int r = 0; r < 8; r++) {
                    float xs = (kk == 0) ? xv[r].x
                             : (kk == 1) ? xv[r].y
                             : (kk == 2) ? xv[r].z : xv[r].w;
                    unsigned long long xx = bcast2(xs);
                    ffma2(acc[r][0], xx, w0.x);
                    ffma2(acc[r][1], xx, w0.y);
                    ffma2(acc[r][2], xx, w1.x);
                    ffma2(acc[r][3], xx, w1.y);
                }
            }
        }

        // ---- bias (+relu on phases 0,1) in place in acc ----
        const float* bias = b3 + ph * 64;
        bool last = (ph == 2);
#pragma unroll
        for (int j = 0; j < 4; j++) {
            float b0 = bias[tx * 8 + 2 * j];
            float b1 = bias[tx * 8 + 2 * j + 1];
#pragma unroll
            for (int r = 0; r < 8; r++) {
                float2 p = *(float2*)&acc[r][j];
                p.x += b0;
                p.y += b1;
                if (!last) {
                    p.x = fmaxf(p.x, 0.f);
                    p.y = fmaxf(p.y, 0.f);
                }
                *(float2*)&acc[r][j] = p;
            }
        }

        if (!last) {
            // writeback into Xs (rows owned by this thread; no sync needed)
#pragma unroll
            for (int r = 0; r < 8; r++) {
                int m = ty * 8 + r;
                int sa = ((2 * tx) ^ ty) & 15;      // m>>3 == ty
                int sb = ((2 * tx + 1) ^ ty) & 15;
                float2 p0 = *(float2*)&acc[r][0];
                float2 p1 = *(float2*)&acc[r][1];
                float2 p2 = *(float2*)&acc[r][2];
                float2 p3 = *(float2*)&acc[r][3];
                *(float4*)&Xs[m * 64 + sa * 4] =
                    make_float4(p0.x, p0.y, p1.x, p1.y);
                *(float4*)&Xs[m * 64 + sb * 4] =
                    make_float4(p2.x, p2.y, p3.x, p3.y);
            }
            __syncthreads();  // drain all Ws reads before reload
            const float4* W4 = (const float4*)(W3 + (ph + 1) * 4096);
            float4* Ws4 = (float4*)Ws;
#pragma unroll
            for (int i = 0; i < 8; i++) Ws4[tid + 128 * i] = W4[tid + 128 * i];
            __syncthreads();
        }
    }

    // ---- epilogue: store Z + BN stats from acc ----
    float s[8], q[8];
#pragma unroll
    for (int j = 0; j < 8; j++) { s[j] = 0.f; q[j] = 0.f; }
#pragma unroll
    for (int r = 0; r < 8; r++) {
        int row = row0 + ty * 8 + r;
        if (row >= NN) continue;
        float2 p0 = *(float2*)&acc[r][0];
        float2 p1 = *(float2*)&acc[r][1];
        float2 p2 = *(float2*)&acc[r][2];
        float2 p3 = *(float2*)&acc[r][3];
        float o[8] = {p0.x, p0.y, p1.x, p1.y, p2.x, p2.y, p3.x, p3.y};
#pragma unroll
        for (int j = 0; j < 8; j++) {
            s[j] += o[j];
            q[j] += o[j] * o[j];
        }
        ((float4*)Z)[(size_t)row * 16 + tx * 2] =
            make_float4(o[0], o[1], o[2], o[3]);
        ((float4*)Z)[(size_t)row * 16 + tx * 2 + 1] =
            make_float4(o[4], o[5], o[6], o[7]);
    }
    {
        __syncthreads();  // Xs reads done (mainloop of last phase)
        float* red = Xs;
#pragma unroll
        for (int j = 0; j < 8; j++) {
            int c = tx * 8 + j;
            red[c * 17 + ty] = s[j];
            red[64 * 17 + c * 17 + ty] = q[j];
        }
        __syncthreads();
        int c = tid & 63;
        int which = tid >> 6;
        float t = 0.f;
#pragma unroll
        for (int i = 0; i < 16; i++) t += red[which * 64 * 17 + c * 17 + i];
        atomicAdd(&g_red[which * 64 + c], t);
    }
}

// ---------------- GEMM (proj / attention / output) ----------------
__global__ void __launch_bounds__(128, 4)
gemm128(const float* __restrict__ X, const float* __restrict__ W,
        const float* __restrict__ bias, float* __restrict__ Y, int M, int relu,
        const float* __restrict__ inscale, const float* __restrict__ inshift,
        int bnstat, const float* __restrict__ seed, float* __restrict__ scout) {
    __shared__ float Ws[64 * 64];
    __shared__ float Xs[128 * 64];
    int tid = threadIdx.x;
    int row0 = blockIdx.x << 7;

    {
        const float4* W4 = (const float4*)W;
        float4* Ws4 = (float4*)Ws;
#pragma unroll
        for (int i = 0; i < 8; i++) Ws4[tid + 128 * i] = W4[tid + 128 * i];
    }
    {
        int c4 = tid & 15;
        int r0 = tid >> 4;
        float4 scl = make_float4(1.f, 1.f, 1.f, 1.f);
        float4 sht = make_float4(0.f, 0.f, 0.f, 0.f);
        if (inscale) {
            scl = ((const float4*)inscale)[c4];
            sht = ((const float4*)inshift)[c4];
        }
#pragma unroll
        for (int i = 0; i < 16; i++) {
            int m = r0 + 8 * i;
            int row = row0 + m;
            float4 v = make_float4(0.f, 0.f, 0.f, 0.f);
            if (row < M) v = ((const float4*)X)[(size_t)row * 16 + c4];
            v.x = v.x * scl.x + sht.x;
            v.y = v.y * scl.y + sht.y;
            v.z = v.z * scl.z + sht.z;
            v.w = v.w * scl.w + sht.w;
            int cs = (c4 ^ (m >> 3)) & 15;
            *(float4*)&Xs[m * 64 + cs * 4] = v;
        }
    }
    __syncthreads();

    int tx = tid & 7;
    int ty = tid >> 3;

    unsigned long long acc[8][4];
#pragma unroll
    for (int r = 0; r < 8; r++)
#pragma unroll
        for (int j = 0; j < 4; j++) acc[r][j] = 0ull;

#pragma unroll
    for (int k4 = 0; k4 < 16; k4++) {
        float4 xv[8];
        int cs = (k4 ^ ty) & 15;
#pragma unroll
        for (int r = 0; r < 8; r++) {
            int m = ty * 8 + r;
            xv[r] = *(const float4*)&Xs[m * 64 + cs * 4];
        }
#pragma unroll
        for (int kk = 0; kk < 4; kk++) {
            int k = k4 * 4 + kk;
            ulonglong2 w0 = *(const ulonglong2*)&Ws[k * 64 + tx * 8];
            ulonglong2 w1 = *(const ulonglong2*)&Ws[k * 64 + tx * 8 + 4];
#pragma unroll
            for (int r = 0; r < 8; r++) {
                float xs = (kk == 0) ? xv[r].x
                         : (kk == 1) ? xv[r].y
                         : (kk == 2) ? xv[r].z : xv[r].w;
                unsigned long long xx = bcast2(xs);
                ffma2(acc[r][0], xx, w0.x);
                ffma2(acc[r][1], xx, w0.y);
                ffma2(acc[r][2], xx, w1.x);
                ffma2(acc[r][3], xx, w1.y);
            }
        }
    }

    float bv[8];
#pragma unroll
    for (int j = 0; j < 8; j++) bv[j] = 0.f;
    if (bias) {
        float4 b0 = ((const float4*)bias)[tx * 2];
        float4 b1 = ((const float4*)bias)[tx * 2 + 1];
        bv[0] = b0.x; bv[1] = b0.y; bv[2] = b0.z; bv[3] = b0.w;
        bv[4] = b1.x; bv[5] = b1.y; bv[6] = b1.z; bv[7] = b1.w;
    }
    float sv[8];
    if (seed) {
#pragma unroll
        for (int j = 0; j < 8; j++) sv[j] = seed[tx * 8 + j];
    }
    float s[8], q[8];
#pragma unroll
    for (int j = 0; j < 8; j++) { s[j] = 0.f; q[j] = 0.f; }

#pragma unroll
    for (int r = 0; r < 8; r++) {
        int row = row0 + ty * 8 + r;
        bool ok = row < M;
        float o[8];
#pragma unroll
        for (int j = 0; j < 4; j++) {
            float2 p = *(float2*)&acc[r][j];
            o[2 * j] = p.x + bv[2 * j];
            o[2 * j + 1] = p.y + bv[2 * j + 1];
        }
        if (relu) {
#pragma unroll
            for (int j = 0; j < 8; j++) o[j] = fmaxf(o[j], 0.f);
        }
        if (bnstat && ok) {
#pragma unroll
            for (int j = 0; j < 8; j++) {
                s[j] += o[j];
                q[j] += o[j] * o[j];
            }
        }
        if (seed) {
            float p = 0.f;
#pragma unroll
            for (int j = 0; j < 8; j++) p += o[j] * sv[j];
            p += __shfl_xor_sync(0xffffffffu, p, 1);
            if (ok && (tx & 1) == 0) scout[row * NH + (tx >> 1)] = p * 0.25f;
        }
        if (ok && Y) {
            ((float4*)Y)[(size_t)row * 16 + tx * 2] =
                make_float4(o[0], o[1], o[2], o[3]);
            ((float4*)Y)[(size_t)row * 16 + tx * 2 + 1] =
                make_float4(o[4], o[5], o[6], o[7]);
        }
    }

    if (bnstat) {
        __syncthreads();
        float* red = Xs;
#pragma unroll
        for (int j = 0; j < 8; j++) {
            int c = tx * 8 + j;
            red[c * 17 + ty] = s[j];
            red[64 * 17 + c * 17 + ty] = q[j];
        }
        __syncthreads();
        {
            int c = tid & 63;
            int which = tid >> 6;
            float t = 0.f;
#pragma unroll
            for (int i = 0; i < 16; i++) t += red[which * 64 * 17 + c * 17 + i];
            atomicAdd(&g_red[which * 64 + c], t);
        }
    }
}

// ---------------- attention readout: one block per graph ----------------
__global__ void k_attn() {
    int g = blockIdx.x;
    int tid = threadIdx.x;  // 128
    int beg = g_goff[g], end = g_goff[g + 1];
    __shared__ float shm[4 * 4];
    __shared__ float shs[4 * 4];
    __shared__ float mx[4], sm[4];
    __shared__ float pacc[64];

    float m0 = -1e30f, m1 = -1e30f, m2 = -1e30f, m3 = -1e30f;
    for (int n = beg + tid; n < end; n += 128) {
        float4 v = ((const float4*)g_sc)[n];
        m0 = fmaxf(m0, v.x); m1 = fmaxf(m1, v.y);
        m2 = fmaxf(m2, v.z); m3 = fmaxf(m3, v.w);
    }
#pragma unroll
    for (int o = 16; o; o >>= 1) {
        m0 = fmaxf(m0, __shfl_xor_sync(0xffffffffu, m0, o));
        m1 = fmaxf(m1, __shfl_xor_sync(0xffffffffu, m1, o));
        m2 = fmaxf(m2, __shfl_xor_sync(0xffffffffu, m2, o));
        m3 = fmaxf(m3, __shfl_xor_sync(0xffffffffu, m3, o));
    }
    if ((tid & 31) == 0) {
        int w = tid >> 5;
        shm[w * 4 + 0] = m0; shm[w * 4 + 1] = m1;
        shm[w * 4 + 2] = m2; shm[w * 4 + 3] = m3;
    }
    __syncthreads();
    if (tid < 4) {
        mx[tid] = fmaxf(fmaxf(shm[tid], shm[4 + tid]),
                        fmaxf(shm[8 + tid], shm[12 + tid]));
    }
    __syncthreads();

    float s0 = 0.f, s1 = 0.f, s2 = 0.f, s3 = 0.f;
    float q0 = mx[0], q1 = mx[1], q2 = mx[2], q3 = mx[3];
    for (int n = beg + tid; n < end; n += 128) {
        float4 v = ((const float4*)g_sc)[n];
        v.x = expf(v.x - q0); v.y = expf(v.y - q1);
        v.z = expf(v.z - q2); v.w = expf(v.w - q3);
        ((float4*)g_sc)[n] = v;
        s0 += v.x; s1 += v.y; s2 += v.z; s3 += v.w;
    }
#pragma unroll
    for (int o = 16; o; o >>= 1) {
        s0 += __shfl_xor_sync(0xffffffffu, s0, o);
        s1 += __shfl_xor_sync(0xffffffffu, s1, o);
        s2 += __shfl_xor_sync(0xffffffffu, s2, o);
        s3 += __shfl_xor_sync(0xffffffffu, s3, o);
    }
    if ((tid & 31) == 0) {
        int w = tid >> 5;
        shs[w * 4 + 0] = s0; shs[w * 4 + 1] = s1;
        shs[w * 4 + 2] = s2; shs[w * 4 + 3] = s3;
    }
    __syncthreads();
    if (tid < 4) {
        float t = shs[tid] + shs[4 + tid] + shs[8 + tid] + shs[12 + tid];
        sm[tid] = (t > 0.f) ? (1.f / t) : 0.f;
    }
    if (tid < 64) pacc[tid] = 0.f;
    __syncthreads();

    int c = tid & 63;
    int half = tid >> 6;
    int hh = c >> 4;
    float acc = 0.f;
    for (int n = beg + half; n < end; n += 2) {
        float w = g_sc[n * NH + hh];
        acc += w * g_agg[(size_t)n * HD + c];
    }
    if (half == 1) atomicAdd(&pacc[c], acc);
    __syncthreads();
    if (half == 0) g_pool[g * HD + c] = (acc + pacc[c]) * sm[hh];
}

__global__ void k_logits(const float* __restrict__ embed,
                         const float* __restrict__ W,
                         const float* __restrict__ b, float* __restrict__ out) {
    int g = blockIdx.x;
    int t = threadIdx.x;  // 128
    __shared__ float e[64];
    if (t < 64) e[t] = embed[g * 64 + t];
    __syncthreads();
    float s = b[t];
#pragma unroll
    for (int k = 0; k < 64; k++) s += e[k] * W[k * NO + t];
    out[g * NO + t] = s;
}

// ---------------- launch ----------------
extern "C" void kernel_launch(void* const* d_in, const int* in_sizes, int n_in,
                              void* d_out, int out_size) {
    const float* x = (const float*)d_in[0];
    const int* ei = (const int*)d_in[1];
    const int* batch = (const int*)d_in[2];
    const float* fng = (const float*)d_in[3];
    const float* fnb = (const float*)d_in[4];
    const float* projW = (const float*)d_in[5];
    const float* projb = (const float*)d_in[6];
    const float* mlpW = (const float*)d_in[7];
    const float* mlpb = (const float*)d_in[8];
    const float* ng = (const float*)d_in[9];
    const float* nb = (const float*)d_in[10];
    const float* seed = (const float*)d_in[11];
    const float* Wk = (const float*)d_in[12];
    const float* Wv = (const float*)d_in[13];
    const float* Wo = (const float*)d_in[14];
    const float* predW = (const float*)d_in[15];
    const float* predb = (const float*)d_in[16];
    float* out = (float*)d_out;

    float *h, *agg, *z, *pool, *bns, *bnt, *sc;
    cudaGetSymbolAddress((void**)&h, g_h);
    cudaGetSymbolAddress((void**)&agg, g_agg);
    cudaGetSymbolAddress((void**)&z, g_z);
    cudaGetSymbolAddress((void**)&pool, g_pool);
    cudaGetSymbolAddress((void**)&bns, g_bns);
    cudaGetSymbolAddress((void**)&bnt, g_bnt);
    cudaGetSymbolAddress((void**)&sc, g_sc);

    const int* src = ei;
    const int* dst = ei + NE;

    const int GB = (NN + 127) / 128;       // 782
    const int EW = (NN * 16 + 255) / 256;
    const int EB = (NE + 255) / 256;
    const int NB = (NN + 255) / 256;
    const int GTB = (NN * 16 + 255) / 256;
    const int NCHUNK = (NN + 1023) / 1024;

    // proj GEMM kept at launch index 3 for the profiler.
    k_bn_stats<<<256, 256>>>(x);
    k_deg_zero<<<NB, 256>>>();
    k_bn_finalize<<<1, 64>>>(fng, fnb, 0);
    gemm128<<<GB, 128>>>(x, projW, projb, h, NN, 1, bns, bnt, 0, nullptr,
                         nullptr);
    k_csr_count<<<EB, 256>>>(dst);
    k_scan_chunk<<<NCHUNK, 256>>>();
    k_scan_tops<<<1, 128>>>(NCHUNK);
    k_scan_final<<<NB, 256>>>();
    k_csr_fill<<<EB, 256>>>(src, dst);
    k_goff<<<NB, 256>>>(batch);

    for (int m = 0; m < 4; m++) {
        const float* Wm = mlpW + m * 3 * 4096;
        const float* bm = mlpb + m * 3 * 64;
        // c = 0: gather(h, plain) -> agg ; fused MLP agg -> z (+BN stats)
        k_gather<<<GTB, 256>>>(h, 0);
        k_mlp3<<<GB, 128>>>(agg, Wm, bm, z);
        k_bn_finalize<<<1, 64>>>(ng + m * 64, nb + m * 64, 0);
        // c = 1: gather(bnrelu(z), slot 0) -> agg ; fused MLP -> z
        k_gather<<<GTB, 256>>>(z, 1);
        k_mlp3<<<GB, 128>>>(agg, Wm, bm, z);
        k_bn_finalize<<<1, 64>>>(ng + m * 64, nb + m * 64, 1);
        // h = relu(bn(z)) + h
        k_resid_fused<<<EW, 256>>>();
    }

    // attention: scores fused into Wk GEMM (K never materialized); V -> agg
    gemm128<<<GB, 128>>>(h, Wk, nullptr, nullptr, NN, 0, nullptr, nullptr, 0,
                         seed, sc);
    gemm128<<<GB, 128>>>(h, Wv, nullptr, agg, NN, 0, nullptr, nullptr, 0,
                         nullptr, nullptr);
    k_attn<<<NG, 128>>>();

    // embed = pooled @ Wo -> d_out[0 : NG*HD)
    gemm128<<<(NG + 127) / 128, 128>>>(pool, Wo, nullptr, out, NG, 0, nullptr,
                                       nullptr, 0, nullptr, nullptr);
    // logits -> d_out[NG*HD : ...)
    k_logits<<<NG, 128>>>(out, predW, predb, out + NG * HD);
}

// round 16
// speedup vs baseline: 1.1061x; 1.0070x over previous
#include <cuda_runtime.h>

#define NN 100000
#define NE 1000000
#define HD 64
#define NG 1000
#define NH 4
#define NO 128

// ---------------- scratch (device globals; no allocation) ----------------
static __device__ float g_h[NN * HD];
static __device__ float g_agg[NN * HD];
static __device__ float g_z[NN * HD];
static __device__ float g_red[2 * HD];     // zero at entry; finalize re-zeroes
static __device__ float g_bns[2 * HD];     // BN scale, 2 slots
static __device__ float g_bnt[2 * HD];     // BN shift, 2 slots
static __device__ float g_sc[NN * NH];
static __device__ float g_pool[NG * HD];
// CSR scratch
static __device__ int g_deg[NN];
static __device__ int g_incl[NN];
static __device__ int g_off[NN + 1];
static __device__ int g_cur[NN];
static __device__ int g_bsum[128];
static __device__ int g_bpre[128];
static __device__ int g_esrc[NE];
static __device__ int g_goff[NG + 1];

// ---------------- f32x2 packed FMA helpers ----------------
__device__ __forceinline__ void ffma2(unsigned long long& d,
                                      unsigned long long a,
                                      unsigned long long b) {
    asm("fma.rn.f32x2 %0, %1, %2, %0;" : "+l"(d) : "l"(a), "l"(b));
}
__device__ __forceinline__ unsigned long long bcast2(float x) {
    unsigned long long r;
    asm("mov.b64 %0, {%1, %1};" : "=l"(r) : "f"(x));
    return r;
}

// ---------------- BatchNorm ----------------
__global__ void k_bn_stats(const float* __restrict__ Z) {
    int f = threadIdx.x & 63;
    int rl = threadIdx.x >> 6;
    float s = 0.f, q = 0.f;
    for (int r = blockIdx.x * 4 + rl; r < NN; r += gridDim.x * 4) {
        float v = Z[(size_t)r * HD + f];
        s += v;
        q += v * v;
    }
    __shared__ float sh[512];
    sh[threadIdx.x] = s;
    sh[256 + threadIdx.x] = q;
    __syncthreads();
    if (rl == 0) {
        s = sh[f] + sh[64 + f] + sh[128 + f] + sh[192 + f];
        q = sh[256 + f] + sh[320 + f] + sh[384 + f] + sh[448 + f];
        atomicAdd(&g_red[f], s);
        atomicAdd(&g_red[64 + f], q);
    }
}

__global__ void k_bn_finalize(const float* __restrict__ gamma,
                              const float* __restrict__ beta, int slot) {
    int f = threadIdx.x;  // 64 threads
    float inv_n = 1.f / (float)NN;
    float mu = g_red[f] * inv_n;
    float var = fmaxf(g_red[64 + f] * inv_n - mu * mu, 0.f);
    float rs = rsqrtf(var + 1e-5f);
    float sc = rs * gamma[f];
    g_bns[slot * 64 + f] = sc;
    g_bnt[slot * 64 + f] = beta[f] - mu * sc;
    g_red[f] = 0.f;
    g_red[64 + f] = 0.f;
}

// h = relu(z*s1+t1) + h   (slot 1; res == h invariant)
__global__ void k_resid_fused() {
    int t = blockIdx.x * blockDim.x + threadIdx.x;
    if (t >= NN * 16) return;
    int c4 = t & 15;
    float4 s = ((const float4*)(g_bns + 64))[c4];
    float4 b = ((const float4*)(g_bnt + 64))[c4];
    float4 v = ((const float4*)g_z)[t];
    float4 r = ((const float4*)g_h)[t];
    float4 a;
    a.x = fmaxf(v.x * s.x + b.x, 0.f) + r.x;
    a.y = fmaxf(v.y * s.y + b.y, 0.f) + r.y;
    a.z = fmaxf(v.z * s.z + b.z, 0.f) + r.z;
    a.w = fmaxf(v.w * s.w + b.w, 0.f) + r.w;
    ((float4*)g_h)[t] = a;
}

// ---------------- CSR build ----------------
__global__ void k_deg_zero() {
    int i = blockIdx.x * blockDim.x + threadIdx.x;
    if (i < NN) g_deg[i] = 0;
}

__global__ void k_csr_count(const int* __restrict__ dst) {
    int e = blockIdx.x * blockDim.x + threadIdx.x;
    if (e < NE) atomicAdd(&g_deg[dst[e]], 1);
}

__global__ void k_scan_chunk() {
    __shared__ int ssum[256];
    int blk = blockIdx.x;
    int base = blk * 1024;
    int tid = threadIdx.x;
    int v[4];
    int s = 0;
#pragma unroll
    for (int j = 0; j < 4; j++) {
        int idx = base + tid * 4 + j;
        int d = (idx < NN) ? g_deg[idx] : 0;
        v[j] = d;
        s += d;
    }
    ssum[tid] = s;
    __syncthreads();
    for (int o = 1; o < 256; o <<= 1) {
        int x = (tid >= o) ? ssum[tid - o] : 0;
        __syncthreads();
        ssum[tid] += x;
        __syncthreads();
    }
    int run = ssum[tid] - s;
#pragma unroll
    for (int j = 0; j < 4; j++) {
        run += v[j];
        int idx = base + tid * 4 + j;
        if (idx < NN) g_incl[idx] = run;
    }
    if (tid == 255) g_bsum[blk] = ssum[255];
}

__global__ void k_scan_tops(int nchunks) {
    __shared__ int sh[128];
    int tid = threadIdx.x;
    int v = (tid < nchunks) ? g_bsum[tid] : 0;
    sh[tid] = v;
    __syncthreads();
    for (int o = 1; o < 128; o <<= 1) {
        int x = (tid >= o) ? sh[tid - o] : 0;
        __syncthreads();
        sh[tid] += x;
        __syncthreads();
    }
    g_bpre[tid] = sh[tid] - v;
}

__global__ void k_scan_final() {
    int i = blockIdx.x * blockDim.x + threadIdx.x;
    if (i == 0) g_off[0] = 0;
    if (i < NN) {
        int off_ip1 = g_incl[i] + g_bpre[i >> 10];
        g_off[i + 1] = off_ip1;
        int off_i = (i == 0) ? 0 : (g_incl[i - 1] + g_bpre[(i - 1) >> 10]);
        g_cur[i] = off_i;
    }
}

__global__ void k_csr_fill(const int* __restrict__ src,
                           const int* __restrict__ dst) {
    int e = blockIdx.x * blockDim.x + threadIdx.x;
    if (e >= NE) return;
    int d = dst[e];
    int pos = atomicAdd(&g_cur[d], 1);
    g_esrc[pos] = src[e];
}

__global__ void k_goff(const int* __restrict__ batch) {
    int i = blockIdx.x * blockDim.x + threadIdx.x;
    if (i >= NN) return;
    int b = batch[i];
    if (i == 0) {
        for (int g = 0; g <= b; g++) g_goff[g] = 0;
    } else {
        int p = batch[i - 1];
        for (int g = p + 1; g <= b; g++) g_goff[g] = i;
    }
    if (i == NN - 1) {
        for (int g = b + 1; g <= NG; g++) g_goff[g] = NN;
    }
}

// ---- gather: agg[n] = f(X[n]) + sum f(X[src]); f = affine+relu if aff ----
__device__ __forceinline__ float4 xf4(float4 v, float4 s, float4 b, int aff) {
    if (!aff) return v;
    float4 o;
    o.x = fmaxf(v.x * s.x + b.x, 0.f);
    o.y = fmaxf(v.y * s.y + b.y, 0.f);
    o.z = fmaxf(v.z * s.z + b.z, 0.f);
    o.w = fmaxf(v.w * s.w + b.w, 0.f);
    return o;
}

__global__ void k_gather(const float* __restrict__ X, int aff) {
    int t = blockIdx.x * blockDim.x + threadIdx.x;
    int n = t >> 4;
    if (n >= NN) return;
    int l = t & 15;
    float4 s = make_float4(1.f, 1.f, 1.f, 1.f);
    float4 b = make_float4(0.f, 0.f, 0.f, 0.f);
    if (aff) {  // slot 0
        s = ((const float4*)g_bns)[l];
        b = ((const float4*)g_bnt)[l];
    }
    int beg = g_off[n], end = g_off[n + 1];
    float4 acc = xf4(((const float4*)X)[(size_t)n * 16 + l], s, b, aff);
    int e = beg;
    for (; e + 4 <= end; e += 4) {
        int s0 = __ldg(&g_esrc[e + 0]);
        int s1 = __ldg(&g_esrc[e + 1]);
        int s2 = __ldg(&g_esrc[e + 2]);
        int s3 = __ldg(&g_esrc[e + 3]);
        float4 v0 = ((const float4*)X)[(size_t)s0 * 16 + l];
        float4 v1 = ((const float4*)X)[(size_t)s1 * 16 + l];
        float4 v2 = ((const float4*)X)[(size_t)s2 * 16 + l];
        float4 v3 = ((const float4*)X)[(size_t)s3 * 16 + l];
        v0 = xf4(v0, s, b, aff);
        v1 = xf4(v1, s, b, aff);
        v2 = xf4(v2, s, b, aff);
        v3 = xf4(v3, s, b, aff);
        acc.x += v0.x + v1.x + v2.x + v3.x;
        acc.y += v0.y + v1.y + v2.y + v3.y;
        acc.z += v0.z + v1.z + v2.z + v3.z;
        acc.w += v0.w + v1.w + v2.w + v3.w;
    }
    for (; e < end; e++) {
        int si = __ldg(&g_esrc[e]);
        float4 v = xf4(((const float4*)X)[(size_t)si * 16 + l], s, b, aff);
        acc.x += v.x; acc.y += v.y; acc.z += v.z; acc.w += v.w;
    }
    ((float4*)g_agg)[(size_t)n * 16 + l] = acc;
}

// ================= fused 3-GEMM MLP (8x8 micro-tile, 128 threads) ========
__global__ void __launch_bounds__(128, 4)
k_mlp3(const float* __restrict__ X, const float* __restrict__ W3,
       const float* __restrict__ b3, float* __restrict__ Z) {
    __shared__ float Ws[64 * 64];
    __shared__ float Xs[128 * 64];
    int tid = threadIdx.x;
    int row0 = blockIdx.x << 7;
    int tx = tid & 7;
    int ty = tid >> 3;

    {
        const float4* W4 = (const float4*)W3;
        float4* Ws4 = (float4*)Ws;
#pragma unroll
        for (int i = 0; i < 8; i++) Ws4[tid + 128 * i] = W4[tid + 128 * i];
    }
    {
        int c4 = tid & 15;
        int r0 = tid >> 4;
#pragma unroll
        for (int i = 0; i < 16; i++) {
            int m = r0 + 8 * i;
            int row = row0 + m;
            float4 v = make_float4(0.f, 0.f, 0.f, 0.f);
            if (row < NN) v = ((const float4*)X)[(size_t)row * 16 + c4];
            int cs = (c4 ^ (m >> 3)) & 15;
            *(float4*)&Xs[m * 64 + cs * 4] = v;
        }
    }
    __syncthreads();

    unsigned long long acc[8][4];

#pragma unroll 1
    for (int ph = 0; ph < 3; ph++) {
#pragma unroll
        for (int r = 0; r < 8; r++)
#pragma unroll
            for (int j = 0; j < 4; j++) acc[r][j] = 0ull;

#pragma unroll
        for (int k4 = 0; k4 < 16; k4++) {
            float4 xv[8];
            int cs = (k4 ^ ty) & 15;
#pragma unroll
            for (int r = 0; r < 8; r++) {
                int m = ty * 8 + r;
                xv[r] = *(const float4*)&Xs[m * 64 + cs * 4];
            }
#pragma unroll
            for (int kk = 0; kk < 4; kk++) {
                int k = k4 * 4 + kk;
                ulonglong2 w0 = *(const ulonglong2*)&Ws[k * 64 + tx * 8];
                ulonglong2 w1 = *(const ulonglong2*)&Ws[k * 64 + tx * 8 + 4];
#pragma unroll
                for (int r = 0; r < 8; r++) {
                    float xs = (kk == 0) ? xv[r].x
                             : (kk == 1) ? xv[r].y
                             : (kk == 2) ? xv[r].z : xv[r].w;
                    unsigned long long xx = bcast2(xs);
                    ffma2(acc[r][0], xx, w0.x);
                    ffma2(acc[r][1], xx, w0.y);
                    ffma2(acc[r][2], xx, w1.x);
                    ffma2(acc[r][3], xx, w1.y);
                }
            }
        }

        const float* bias = b3 + ph * 64;
        bool last = (ph == 2);
#pragma unroll
        for (int j = 0; j < 4; j++) {
            float b0 = bias[tx * 8 + 2 * j];
            float b1 = bias[tx * 8 + 2 * j + 1];
#pragma unroll
            for (int r = 0; r < 8; r++) {
                float2 p = *(float2*)&acc[r][j];
                p.x += b0;
                p.y += b1;
                if (!last) {
                    p.x = fmaxf(p.x, 0.f);
                    p.y = fmaxf(p.y, 0.f);
                }
                *(float2*)&acc[r][j] = p;
            }
        }

        if (!last) {
#pragma unroll
            for (int r = 0; r < 8; r++) {
                int m = ty * 8 + r;
                int sa = ((2 * tx) ^ ty) & 15;
                int sb = ((2 * tx + 1) ^ ty) & 15;
                float2 p0 = *(float2*)&acc[r][0];
                float2 p1 = *(float2*)&acc[r][1];
                float2 p2 = *(float2*)&acc[r][2];
                float2 p3 = *(float2*)&acc[r][3];
                *(float4*)&Xs[m * 64 + sa * 4] =
                    make_float4(p0.x, p0.y, p1.x, p1.y);
                *(float4*)&Xs[m * 64 + sb * 4] =
                    make_float4(p2.x, p2.y, p3.x, p3.y);
            }
            __syncthreads();
            const float4* W4 = (const float4*)(W3 + (ph + 1) * 4096);
            float4* Ws4 = (float4*)Ws;
#pragma unroll
            for (int i = 0; i < 8; i++) Ws4[tid + 128 * i] = W4[tid + 128 * i];
            __syncthreads();
        }
    }

    float s[8], q[8];
#pragma unroll
    for (int j = 0; j < 8; j++) { s[j] = 0.f; q[j] = 0.f; }
#pragma unroll
    for (int r = 0; r < 8; r++) {
        int row = row0 + ty * 8 + r;
        if (row >= NN) continue;
        float2 p0 = *(float2*)&acc[r][0];
        float2 p1 = *(float2*)&acc[r][1];
        float2 p2 = *(float2*)&acc[r][2];
        float2 p3 = *(float2*)&acc[r][3];
        float o[8] = {p0.x, p0.y, p1.x, p1.y, p2.x, p2.y, p3.x, p3.y};
#pragma unroll
        for (int j = 0; j < 8; j++) {
            s[j] += o[j];
            q[j] += o[j] * o[j];
        }
        ((float4*)Z)[(size_t)row * 16 + tx * 2] =
            make_float4(o[0], o[1], o[2], o[3]);
        ((float4*)Z)[(size_t)row * 16 + tx * 2 + 1] =
            make_float4(o[4], o[5], o[6], o[7]);
    }
    {
        __syncthreads();
        float* red = Xs;
#pragma unroll
        for (int j = 0; j < 8; j++) {
            int c = tx * 8 + j;
            red[c * 17 + ty] = s[j];
            red[64 * 17 + c * 17 + ty] = q[j];
        }
        __syncthreads();
        int c = tid & 63;
        int which = tid >> 6;
        float t = 0.f;
#pragma unroll
        for (int i = 0; i < 16; i++) t += red[which * 64 * 17 + c * 17 + i];
        atomicAdd(&g_red[which * 64 + c], t);
    }
}

// ============ fused attention K/V: one tile load, two GEMM phases ========
// Phase 0: V = h @ Wv -> g_agg.  Phase 1: scores = (h @ Wk) . seed -> g_sc.
__global__ void __launch_bounds__(128, 4)
k_kv(const float* __restrict__ X, const float* __restrict__ Wv,
     const float* __restrict__ Wk, const float* __restrict__ seed) {
    __shared__ float Ws[64 * 64];
    __shared__ float Xs[128 * 64];
    int tid = threadIdx.x;
    int row0 = blockIdx.x << 7;
    int tx = tid & 7;
    int ty = tid >> 3;

    {
        const float4* W4 = (const float4*)Wv;
        float4* Ws4 = (float4*)Ws;
#pragma unroll
        for (int i = 0; i < 8; i++) Ws4[tid + 128 * i] = W4[tid + 128 * i];
    }
    {
        int c4 = tid & 15;
        int r0 = tid >> 4;
#pragma unroll
        for (int i = 0; i < 16; i++) {
            int m = r0 + 8 * i;
            int row = row0 + m;
            float4 v = make_float4(0.f, 0.f, 0.f, 0.f);
            if (row < NN) v = ((const float4*)X)[(size_t)row * 16 + c4];
            int cs = (c4 ^ (m >> 3)) & 15;
            *(float4*)&Xs[m * 64 + cs * 4] = v;
        }
    }
    __syncthreads();

    unsigned long long acc[8][4];

#pragma unroll 1
    for (int ph = 0; ph < 2; ph++) {
#pragma unroll
        for (int r = 0; r < 8; r++)
#pragma unroll
            for (int j = 0; j < 4; j++) acc[r][j] = 0ull;

#pragma unroll
        for (int k4 = 0; k4 < 16; k4++) {
            float4 xv[8];
            int cs = (k4 ^ ty) & 15;
#pragma unroll
            for (int r = 0; r < 8; r++) {
                int m = ty * 8 + r;
                xv[r] = *(const float4*)&Xs[m * 64 + cs * 4];
            }
#pragma unroll
            for (int kk = 0; kk < 4; kk++) {
                int k = k4 * 4 + kk;
                ulonglong2 w0 = *(const ulonglong2*)&Ws[k * 64 + tx * 8];
                ulonglong2 w1 = *(const ulonglong2*)&Ws[k * 64 + tx * 8 + 4];
#pragma unroll
                for (int r = 0; r < 8; r++) {
                    float xs = (kk == 0) ? xv[r].x
                             : (kk == 1) ? xv[r].y
                             : (kk == 2) ? xv[r].z : xv[r].w;
                    unsigned long long xx = bcast2(xs);
                    ffma2(acc[r][0], xx, w0.x);
                    ffma2(acc[r][1], xx, w0.y);
                    ffma2(acc[r][2], xx, w1.x);
                    ffma2(acc[r][3], xx, w1.y);
                }
            }
        }

        if (ph == 0) {
            // V -> g_agg; then reload Ws with Wk (Xs untouched)
#pragma unroll
            for (int r = 0; r < 8; r++) {
                int row = row0 + ty * 8 + r;
                if (row >= NN) continue;
                float2 p0 = *(float2*)&acc[r][0];
                float2 p1 = *(float2*)&acc[r][1];
                float2 p2 = *(float2*)&acc[r][2];
                float2 p3 = *(float2*)&acc[r][3];
                ((float4*)g_agg)[(size_t)row * 16 + tx * 2] =
                    make_float4(p0.x, p0.y, p1.x, p1.y);
                ((float4*)g_agg)[(size_t)row * 16 + tx * 2 + 1] =
                    make_float4(p2.x, p2.y, p3.x, p3.y);
            }
            __syncthreads();  // drain Ws reads
            const float4* W4 = (const float4*)Wk;
            float4* Ws4 = (float4*)Ws;
#pragma unroll
            for (int i = 0; i < 8; i++) Ws4[tid + 128 * i] = W4[tid + 128 * i];
            __syncthreads();
        } else {
            // scores: per-row dot of this thread's 8 cols with seed
            float sv[8];
#pragma unroll
            for (int j = 0; j < 8; j++) sv[j] = seed[tx * 8 + j];
#pragma unroll
            for (int r = 0; r < 8; r++) {
                int row = row0 + ty * 8 + r;
                float2 p0 = *(float2*)&acc[r][0];
                float2 p1 = *(float2*)&acc[r][1];
                float2 p2 = *(float2*)&acc[r][2];
                float2 p3 = *(float2*)&acc[r][3];
                float p = p0.x * sv[0] + p0.y * sv[1] + p1.x * sv[2] +
                          p1.y * sv[3] + p2.x * sv[4] + p2.y * sv[5] +
                          p3.x * sv[6] + p3.y * sv[7];
                p += __shfl_xor_sync(0xffffffffu, p, 1);
                if (row < NN && (tx & 1) == 0)
                    g_sc[row * NH + (tx >> 1)] = p * 0.25f;
            }
        }
    }
}

// ---------------- GEMM (proj / output) ----------------
__global__ void __launch_bounds__(128, 4)
gemm128(const float* __restrict__ X, const float* __restrict__ W,
        const float* __restrict__ bias, float* __restrict__ Y, int M, int relu,
        const float* __restrict__ inscale, const float* __restrict__ inshift) {
    __shared__ float Ws[64 * 64];
    __shared__ float Xs[128 * 64];
    int tid = threadIdx.x;
    int row0 = blockIdx.x << 7;

    {
        const float4* W4 = (const float4*)W;
        float4* Ws4 = (float4*)Ws;
#pragma unroll
        for (int i = 0; i < 8; i++) Ws4[tid + 128 * i] = W4[tid + 128 * i];
    }
    {
        int c4 = tid & 15;
        int r0 = tid >> 4;
        float4 scl = make_float4(1.f, 1.f, 1.f, 1.f);
        float4 sht = make_float4(0.f, 0.f, 0.f, 0.f);
        if (inscale) {
            scl = ((const float4*)inscale)[c4];
            sht = ((const float4*)inshift)[c4];
        }
#pragma unroll
        for (int i = 0; i < 16; i++) {
            int m = r0 + 8 * i;
            int row = row0 + m;
            float4 v = make_float4(0.f, 0.f, 0.f, 0.f);
            if (row < M) v = ((const float4*)X)[(size_t)row * 16 + c4];
            v.x = v.x * scl.x + sht.x;
            v.y = v.y * scl.y + sht.y;
            v.z = v.z * scl.z + sht.z;
            v.w = v.w * scl.w + sht.w;
            int cs = (c4 ^ (m >> 3)) & 15;
            *(float4*)&Xs[m * 64 + cs * 4] = v;
        }
    }
    __syncthreads();

    int tx = tid & 7;
    int ty = tid >> 3;

    unsigned long long acc[8][4];
#pragma unroll
    for (int r = 0; r < 8; r++)
#pragma unroll
        for (int j = 0; j < 4; j++) acc[r][j] = 0ull;

#pragma unroll
    for (int k4 = 0; k4 < 16; k4++) {
        float4 xv[8];
        int cs = (k4 ^ ty) & 15;
#pragma unroll
        for (int r = 0; r < 8; r++) {
            int m = ty * 8 + r;
            xv[r] = *(const float4*)&Xs[m * 64 + cs * 4];
        }
#pragma unroll
        for (int kk = 0; kk < 4; kk++) {
            int k = k4 * 4 + kk;
            ulonglong2 w0 = *(const ulonglong2*)&Ws[k * 64 + tx * 8];
            ulonglong2 w1 = *(const ulonglong2*)&Ws[k * 64 + tx * 8 + 4];
#pragma unroll
            for (int r = 0; r < 8; r++) {
                float xs = (kk == 0) ? xv[r].x
                         : (kk == 1) ? xv[r].y
                         : (kk == 2) ? xv[r].z : xv[r].w;
                unsigned long long xx = bcast2(xs);
                ffma2(acc[r][0], xx, w0.x);
                ffma2(acc[r][1], xx, w0.y);
                ffma2(acc[r][2], xx, w1.x);
                ffma2(acc[r][3], xx, w1.y);
            }
        }
    }

    float bv[8];
#pragma unroll
    for (int j = 0; j < 8; j++) bv[j] = 0.f;
    if (bias) {
        float4 b0 = ((const float4*)bias)[tx * 2];
        float4 b1 = ((const float4*)bias)[tx * 2 + 1];
        bv[0] = b0.x; bv[1] = b0.y; bv[2] = b0.z; bv[3] = b0.w;
        bv[4] = b1.x; bv[5] = b1.y; bv[6] = b1.z; bv[7] = b1.w;
    }

#pragma unroll
    for (int r = 0; r < 8; r++) {
        int row = row0 + ty * 8 + r;
        if (row >= M) continue;
        float o[8];
#pragma unroll
        for (int j = 0; j < 4; j++) {
            float2 p = *(float2*)&acc[r][j];
            o[2 * j] = p.x + bv[2 * j];
            o[2 * j + 1] = p.y + bv[2 * j + 1];
        }
        if (relu) {
#pragma unroll
            for (int j = 0; j < 8; j++) o[j] = fmaxf(o[j], 0.f);
        }
        ((float4*)Y)[(size_t)row * 16 + tx * 2] =
            make_float4(o[0], o[1], o[2], o[3]);
        ((float4*)Y)[(size_t)row * 16 + tx * 2 + 1] =
            make_float4(o[4], o[5], o[6], o[7]);
    }
}

// ---------------- attention readout: one block per graph ----------------
__global__ void k_attn() {
    int g = blockIdx.x;
    int tid = threadIdx.x;  // 128
    int beg = g_goff[g], end = g_goff[g + 1];
    __shared__ float shm[4 * 4];
    __shared__ float shs[4 * 4];
    __shared__ float mx[4], sm[4];
    __shared__ float pacc[64];

    float m0 = -1e30f, m1 = -1e30f, m2 = -1e30f, m3 = -1e30f;
    for (int n = beg + tid; n < end; n += 128) {
        float4 v = ((const float4*)g_sc)[n];
        m0 = fmaxf(m0, v.x); m1 = fmaxf(m1, v.y);
        m2 = fmaxf(m2, v.z); m3 = fmaxf(m3, v.w);
    }
#pragma unroll
    for (int o = 16; o; o >>= 1) {
        m0 = fmaxf(m0, __shfl_xor_sync(0xffffffffu, m0, o));
        m1 = fmaxf(m1, __shfl_xor_sync(0xffffffffu, m1, o));
        m2 = fmaxf(m2, __shfl_xor_sync(0xffffffffu, m2, o));
        m3 = fmaxf(m3, __shfl_xor_sync(0xffffffffu, m3, o));
    }
    if ((tid & 31) == 0) {
        int w = tid >> 5;
        shm[w * 4 + 0] = m0; shm[w * 4 + 1] = m1;
        shm[w * 4 + 2] = m2; shm[w * 4 + 3] = m3;
    }
    __syncthreads();
    if (tid < 4) {
        mx[tid] = fmaxf(fmaxf(shm[tid], shm[4 + tid]),
                        fmaxf(shm[8 + tid], shm[12 + tid]));
    }
    __syncthreads();

    float s0 = 0.f, s1 = 0.f, s2 = 0.f, s3 = 0.f;
    float q0 = mx[0], q1 = mx[1], q2 = mx[2], q3 = mx[3];
    for (int n = beg + tid; n < end; n += 128) {
        float4 v = ((const float4*)g_sc)[n];
        v.x = expf(v.x - q0); v.y = expf(v.y - q1);
        v.z = expf(v.z - q2); v.w = expf(v.w - q3);
        ((float4*)g_sc)[n] = v;
        s0 += v.x; s1 += v.y; s2 += v.z; s3 += v.w;
    }
#pragma unroll
    for (int o = 16; o; o >>= 1) {
        s0 += __shfl_xor_sync(0xffffffffu, s0, o);
        s1 += __shfl_xor_sync(0xffffffffu, s1, o);
        s2 += __shfl_xor_sync(0xffffffffu, s2, o);
        s3 += __shfl_xor_sync(0xffffffffu, s3, o);
    }
    if ((tid & 31) == 0) {
        int w = tid >> 5;
        shs[w * 4 + 0] = s0; shs[w * 4 + 1] = s1;
        shs[w * 4 + 2] = s2; shs[w * 4 + 3] = s3;
    }
    __syncthreads();
    if (tid < 4) {
        float t = shs[tid] + shs[4 + tid] + shs[8 + tid] + shs[12 + tid];
        sm[tid] = (t > 0.f) ? (1.f / t) : 0.f;
    }
    if (tid < 64) pacc[tid] = 0.f;
    __syncthreads();

    int c = tid & 63;
    int half = tid >> 6;
    int hh = c >> 4;
    float acc = 0.f;
    for (int n = beg + half; n < end; n += 2) {
        float w = g_sc[n * NH + hh];
        acc += w * g_agg[(size_t)n * HD + c];
    }
    if (half == 1) atomicAdd(&pacc[c], acc);
    __syncthreads();
    if (half == 0) g_pool[g * HD + c] = (acc + pacc[c]) * sm[hh];
}

__global__ void k_logits(const float* __restrict__ embed,
                         const float* __restrict__ W,
                         const float* __restrict__ b, float* __restrict__ out) {
    int g = blockIdx.x;
    int t = threadIdx.x;  // 128
    __shared__ float e[64];
    if (t < 64) e[t] = embed[g * 64 + t];
    __syncthreads();
    float s = b[t];
#pragma unroll
    for (int k = 0; k < 64; k++) s += e[k] * W[k * NO + t];
    out[g * NO + t] = s;
}

// ---------------- launch ----------------
extern "C" void kernel_launch(void* const* d_in, const int* in_sizes, int n_in,
                              void* d_out, int out_size) {
    const float* x = (const float*)d_in[0];
    const int* ei = (const int*)d_in[1];
    const int* batch = (const int*)d_in[2];
    const float* fng = (const float*)d_in[3];
    const float* fnb = (const float*)d_in[4];
    const float* projW = (const float*)d_in[5];
    const float* projb = (const float*)d_in[6];
    const float* mlpW = (const float*)d_in[7];
    const float* mlpb = (const float*)d_in[8];
    const float* ng = (const float*)d_in[9];
    const float* nb = (const float*)d_in[10];
    const float* seed = (const float*)d_in[11];
    const float* Wk = (const float*)d_in[12];
    const float* Wv = (const float*)d_in[13];
    const float* Wo = (const float*)d_in[14];
    const float* predW = (const float*)d_in[15];
    const float* predb = (const float*)d_in[16];
    float* out = (float*)d_out;

    float *h, *agg, *z, *pool, *bns, *bnt;
    cudaGetSymbolAddress((void**)&h, g_h);
    cudaGetSymbolAddress((void**)&agg, g_agg);
    cudaGetSymbolAddress((void**)&z, g_z);
    cudaGetSymbolAddress((void**)&pool, g_pool);
    cudaGetSymbolAddress((void**)&bns, g_bns);
    cudaGetSymbolAddress((void**)&bnt, g_bnt);

    const int* src = ei;
    const int* dst = ei + NE;

    const int GB = (NN + 127) / 128;       // 782
    const int EW = (NN * 16 + 255) / 256;
    const int EB = (NE + 255) / 256;
    const int NB = (NN + 255) / 256;
    const int GTB = (NN * 16 + 255) / 256;
    const int NCHUNK = (NN + 1023) / 1024;

    // proj GEMM kept at launch index 3 for the profiler.
    k_bn_stats<<<256, 256>>>(x);
    k_deg_zero<<<NB, 256>>>();
    k_bn_finalize<<<1, 64>>>(fng, fnb, 0);
    gemm128<<<GB, 128>>>(x, projW, projb, h, NN, 1, bns, bnt);
    k_csr_count<<<EB, 256>>>(dst);
    k_scan_chunk<<<NCHUNK, 256>>>();
    k_scan_tops<<<1, 128>>>(NCHUNK);
    k_scan_final<<<NB, 256>>>();
    k_csr_fill<<<EB, 256>>>(src, dst);
    k_goff<<<NB, 256>>>(batch);

    for (int m = 0; m < 4; m++) {
        const float* Wm = mlpW + m * 3 * 4096;
        const float* bm = mlpb + m * 3 * 64;
        // c = 0: gather(h, plain) -> agg ; fused MLP agg -> z (+BN stats)
        k_gather<<<GTB, 256>>>(h, 0);
        k_mlp3<<<GB, 128>>>(agg, Wm, bm, z);
        k_bn_finalize<<<1, 64>>>(ng + m * 64, nb + m * 64, 0);
        // c = 1: gather(bnrelu(z), slot 0) -> agg ; fused MLP -> z
        k_gather<<<GTB, 256>>>(z, 1);
        k_mlp3<<<GB, 128>>>(agg, Wm, bm, z);
        k_bn_finalize<<<1, 64>>>(ng + m * 64, nb + m * 64, 1);
        // h = relu(bn(z)) + h
        k_resid_fused<<<EW, 256>>>();
    }

    // attention: fused K/V (V -> agg, scores -> g_sc; one tile load)
    k_kv<<<GB, 128>>>(h, Wv, Wk, seed);
    k_attn<<<NG, 128>>>();

    // embed = pooled @ Wo -> d_out[0 : NG*HD)
    gemm128<<<(NG + 127) / 128, 128>>>(pool, Wo, nullptr, out, NG, 0, nullptr,
                                       nullptr);
    // logits -> d_out[NG*HD : ...)
    k_logits<<<NG, 128>>>(out, predW, predb, out + NG * HD);
}

// round 17
// speedup vs baseline: 1.1078x; 1.0015x over previous
#include <cuda_runtime.h>

#define NN 100000
#define NE 1000000
#define HD 64
#define NG 1000
#define NH 4
#define NO 128

// ---------------- scratch (device globals; no allocation) ----------------
static __device__ float g_h[NN * HD];
static __device__ float g_agg[NN * HD];
static __device__ float g_z[NN * HD];
static __device__ float g_red[2 * HD];     // zero at entry; finalize re-zeroes
static __device__ float g_bns[2 * HD];     // BN scale, 2 slots
static __device__ float g_bnt[2 * HD];     // BN shift, 2 slots
static __device__ float g_sc[NN * NH];
static __device__ float g_pool[NG * HD];
// CSR scratch
static __device__ int g_deg[NN];
static __device__ int g_incl[NN];
static __device__ int g_off[NN + 1];
static __device__ int g_cur[NN];
static __device__ int g_bsum[128];
static __device__ int g_bpre[128];
static __device__ int g_esrc[NE];
static __device__ int g_goff[NG + 1];

// ---------------- f32x2 packed FMA helpers ----------------
__device__ __forceinline__ void ffma2(unsigned long long& d,
                                      unsigned long long a,
                                      unsigned long long b) {
    asm("fma.rn.f32x2 %0, %1, %2, %0;" : "+l"(d) : "l"(a), "l"(b));
}
__device__ __forceinline__ unsigned long long bcast2(float x) {
    unsigned long long r;
    asm("mov.b64 %0, {%1, %1};" : "=l"(r) : "f"(x));
    return r;
}

// ---------------- BatchNorm stats (+ fold in deg zeroing) ----------------
__global__ void k_bn_stats(const float* __restrict__ Z) {
    // fold: zero g_deg (runs before k_csr_count in program order)
    for (int i = blockIdx.x * blockDim.x + threadIdx.x; i < NN;
         i += gridDim.x * blockDim.x)
        g_deg[i] = 0;
    int f = threadIdx.x & 63;
    int rl = threadIdx.x >> 6;
    float s = 0.f, q = 0.f;
    for (int r = blockIdx.x * 4 + rl; r < NN; r += gridDim.x * 4) {
        float v = Z[(size_t)r * HD + f];
        s += v;
        q += v * v;
    }
    __shared__ float sh[512];
    sh[threadIdx.x] = s;
    sh[256 + threadIdx.x] = q;
    __syncthreads();
    if (rl == 0) {
        s = sh[f] + sh[64 + f] + sh[128 + f] + sh[192 + f];
        q = sh[256 + f] + sh[320 + f] + sh[384 + f] + sh[448 + f];
        atomicAdd(&g_red[f], s);
        atomicAdd(&g_red[64 + f], q);
    }
}

__global__ void k_bn_finalize(const float* __restrict__ gamma,
                              const float* __restrict__ beta, int slot) {
    int f = threadIdx.x;  // 64 threads
    float inv_n = 1.f / (float)NN;
    float mu = g_red[f] * inv_n;
    float var = fmaxf(g_red[64 + f] * inv_n - mu * mu, 0.f);
    float rs = rsqrtf(var + 1e-5f);
    float sc = rs * gamma[f];
    g_bns[slot * 64 + f] = sc;
    g_bnt[slot * 64 + f] = beta[f] - mu * sc;
    g_red[f] = 0.f;
    g_red[64 + f] = 0.f;
}

// h = relu(z*s1+t1) + h   (slot 1; res == h invariant)
__global__ void k_resid_fused() {
    int t = blockIdx.x * blockDim.x + threadIdx.x;
    if (t >= NN * 16) return;
    int c4 = t & 15;
    float4 s = ((const float4*)(g_bns + 64))[c4];
    float4 b = ((const float4*)(g_bnt + 64))[c4];
    float4 v = ((const float4*)g_z)[t];
    float4 r = ((const float4*)g_h)[t];
    float4 a;
    a.x = fmaxf(v.x * s.x + b.x, 0.f) + r.x;
    a.y = fmaxf(v.y * s.y + b.y, 0.f) + r.y;
    a.z = fmaxf(v.z * s.z + b.z, 0.f) + r.z;
    a.w = fmaxf(v.w * s.w + b.w, 0.f) + r.w;
    ((float4*)g_h)[t] = a;
}

// ---------------- CSR build ----------------
__global__ void k_csr_count(const int* __restrict__ dst) {
    int e = blockIdx.x * blockDim.x + threadIdx.x;
    if (e < NE) atomicAdd(&g_deg[dst[e]], 1);
}

__global__ void k_scan_chunk() {
    __shared__ int ssum[256];
    int blk = blockIdx.x;
    int base = blk * 1024;
    int tid = threadIdx.x;
    int v[4];
    int s = 0;
#pragma unroll
    for (int j = 0; j < 4; j++) {
        int idx = base + tid * 4 + j;
        int d = (idx < NN) ? g_deg[idx] : 0;
        v[j] = d;
        s += d;
    }
    ssum[tid] = s;
    __syncthreads();
    for (int o = 1; o < 256; o <<= 1) {
        int x = (tid >= o) ? ssum[tid - o] : 0;
        __syncthreads();
        ssum[tid] += x;
        __syncthreads();
    }
    int run = ssum[tid] - s;
#pragma unroll
    for (int j = 0; j < 4; j++) {
        run += v[j];
        int idx = base + tid * 4 + j;
        if (idx < NN) g_incl[idx] = run;
    }
    if (tid == 255) g_bsum[blk] = ssum[255];
}

__global__ void k_scan_tops(int nchunks) {
    __shared__ int sh[128];
    int tid = threadIdx.x;
    int v = (tid < nchunks) ? g_bsum[tid] : 0;
    sh[tid] = v;
    __syncthreads();
    for (int o = 1; o < 128; o <<= 1) {
        int x = (tid >= o) ? sh[tid - o] : 0;
        __syncthreads();
        sh[tid] += x;
        __syncthreads();
    }
    g_bpre[tid] = sh[tid] - v;
}

__global__ void k_scan_final() {
    int i = blockIdx.x * blockDim.x + threadIdx.x;
    if (i == 0) g_off[0] = 0;
    if (i < NN) {
        int off_ip1 = g_incl[i] + g_bpre[i >> 10];
        g_off[i + 1] = off_ip1;
        int off_i = (i == 0) ? 0 : (g_incl[i - 1] + g_bpre[(i - 1) >> 10]);
        g_cur[i] = off_i;
    }
}

__global__ void k_csr_fill(const int* __restrict__ src,
                           const int* __restrict__ dst) {
    int e = blockIdx.x * blockDim.x + threadIdx.x;
    if (e >= NE) return;
    int d = dst[e];
    int pos = atomicAdd(&g_cur[d], 1);
    g_esrc[pos] = src[e];
}

__global__ void k_goff(const int* __restrict__ batch) {
    int i = blockIdx.x * blockDim.x + threadIdx.x;
    if (i >= NN) return;
    int b = batch[i];
    if (i == 0) {
        for (int g = 0; g <= b; g++) g_goff[g] = 0;
    } else {
        int p = batch[i - 1];
        for (int g = p + 1; g <= b; g++) g_goff[g] = i;
    }
    if (i == NN - 1) {
        for (int g = b + 1; g <= NG; g++) g_goff[g] = NN;
    }
}

// ---- gather: agg[n] = f(X[n]) + sum f(X[src]); f = affine+relu if aff ----
__device__ __forceinline__ float4 xf4(float4 v, float4 s, float4 b, int aff) {
    if (!aff) return v;
    float4 o;
    o.x = fmaxf(v.x * s.x + b.x, 0.f);
    o.y = fmaxf(v.y * s.y + b.y, 0.f);
    o.z = fmaxf(v.z * s.z + b.z, 0.f);
    o.w = fmaxf(v.w * s.w + b.w, 0.f);
    return o;
}

__global__ void k_gather(const float* __restrict__ X, int aff) {
    int t = blockIdx.x * blockDim.x + threadIdx.x;
    int n = t >> 4;
    if (n >= NN) return;
    int l = t & 15;
    float4 s = make_float4(1.f, 1.f, 1.f, 1.f);
    float4 b = make_float4(0.f, 0.f, 0.f, 0.f);
    if (aff) {  // slot 0
        s = ((const float4*)g_bns)[l];
        b = ((const float4*)g_bnt)[l];
    }
    int beg = g_off[n], end = g_off[n + 1];
    float4 acc = xf4(((const float4*)X)[(size_t)n * 16 + l], s, b, aff);
    int e = beg;
    for (; e + 4 <= end; e += 4) {
        int s0 = __ldg(&g_esrc[e + 0]);
        int s1 = __ldg(&g_esrc[e + 1]);
        int s2 = __ldg(&g_esrc[e + 2]);
        int s3 = __ldg(&g_esrc[e + 3]);
        float4 v0 = ((const float4*)X)[(size_t)s0 * 16 + l];
        float4 v1 = ((const float4*)X)[(size_t)s1 * 16 + l];
        float4 v2 = ((const float4*)X)[(size_t)s2 * 16 + l];
        float4 v3 = ((const float4*)X)[(size_t)s3 * 16 + l];
        v0 = xf4(v0, s, b, aff);
        v1 = xf4(v1, s, b, aff);
        v2 = xf4(v2, s, b, aff);
        v3 = xf4(v3, s, b, aff);
        acc.x += v0.x + v1.x + v2.x + v3.x;
        acc.y += v0.y + v1.y + v2.y + v3.y;
        acc.z += v0.z + v1.z + v2.z + v3.z;
        acc.w += v0.w + v1.w + v2.w + v3.w;
    }
    for (; e < end; e++) {
        int si = __ldg(&g_esrc[e]);
        float4 v = xf4(((const float4*)X)[(size_t)si * 16 + l], s, b, aff);
        acc.x += v.x; acc.y += v.y; acc.z += v.z; acc.w += v.w;
    }
    ((float4*)g_agg)[(size_t)n * 16 + l] = acc;
}

// ================= fused 3-GEMM MLP (8x8 micro-tile, 128 threads) ========
__global__ void __launch_bounds__(128, 4)
k_mlp3(const float* __restrict__ X, const float* __restrict__ W3,
       const float* __restrict__ b3, float* __restrict__ Z) {
    __shared__ float Ws[64 * 64];
    __shared__ float Xs[128 * 64];
    int tid = threadIdx.x;
    int row0 = blockIdx.x << 7;
    int tx = tid & 7;
    int ty = tid >> 3;

    {
        const float4* W4 = (const float4*)W3;
        float4* Ws4 = (float4*)Ws;
#pragma unroll
        for (int i = 0; i < 8; i++) Ws4[tid + 128 * i] = W4[tid + 128 * i];
    }
    {
        int c4 = tid & 15;
        int r0 = tid >> 4;
#pragma unroll
        for (int i = 0; i < 16; i++) {
            int m = r0 + 8 * i;
            int row = row0 + m;
            float4 v = make_float4(0.f, 0.f, 0.f, 0.f);
            if (row < NN) v = ((const float4*)X)[(size_t)row * 16 + c4];
            int cs = (c4 ^ (m >> 3)) & 15;
            *(float4*)&Xs[m * 64 + cs * 4] = v;
        }
    }
    __syncthreads();

    unsigned long long acc[8][4];

#pragma unroll 1
    for (int ph = 0; ph < 3; ph++) {
#pragma unroll
        for (int r = 0; r < 8; r++)
#pragma unroll
            for (int j = 0; j < 4; j++) acc[r][j] = 0ull;

#pragma unroll
        for (int k4 = 0; k4 < 16; k4++) {
            float4 xv[8];
            int cs = (k4 ^ ty) & 15;
#pragma unroll
            for (int r = 0; r < 8; r++) {
                int m = ty * 8 + r;
                xv[r] = *(const float4*)&Xs[m * 64 + cs * 4];
            }
#pragma unroll
            for (int kk = 0; kk < 4; kk++) {
                int k = k4 * 4 + kk;
                ulonglong2 w0 = *(const ulonglong2*)&Ws[k * 64 + tx * 8];
                ulonglong2 w1 = *(const ulonglong2*)&Ws[k * 64 + tx * 8 + 4];
#pragma unroll
                for (int r = 0; r < 8; r++) {
                    float xs = (kk == 0) ? xv[r].x
                             : (kk == 1) ? xv[r].y
                             : (kk == 2) ? xv[r].z : xv[r].w;
                    unsigned long long xx = bcast2(xs);
                    ffma2(acc[r][0], xx, w0.x);
                    ffma2(acc[r][1], xx, w0.y);
                    ffma2(acc[r][2], xx, w1.x);
                    ffma2(acc[r][3], xx, w1.y);
                }
            }
        }

        const float* bias = b3 + ph * 64;
        bool last = (ph == 2);
#pragma unroll
        for (int j = 0; j < 4; j++) {
            float b0 = bias[tx * 8 + 2 * j];
            float b1 = bias[tx * 8 + 2 * j + 1];
#pragma unroll
            for (int r = 0; r < 8; r++) {
                float2 p = *(float2*)&acc[r][j];
                p.x += b0;
                p.y += b1;
                if (!last) {
                    p.x = fmaxf(p.x, 0.f);
                    p.y = fmaxf(p.y, 0.f);
                }
                *(float2*)&acc[r][j] = p;
            }
        }

        if (!last) {
#pragma unroll
            for (int r = 0; r < 8; r++) {
                int m = ty * 8 + r;
                int sa = ((2 * tx) ^ ty) & 15;
                int sb = ((2 * tx + 1) ^ ty) & 15;
                float2 p0 = *(float2*)&acc[r][0];
                float2 p1 = *(float2*)&acc[r][1];
                float2 p2 = *(float2*)&acc[r][2];
                float2 p3 = *(float2*)&acc[r][3];
                *(float4*)&Xs[m * 64 + sa * 4] =
                    make_float4(p0.x, p0.y, p1.x, p1.y);
                *(float4*)&Xs[m * 64 + sb * 4] =
                    make_float4(p2.x, p2.y, p3.x, p3.y);
            }
            __syncthreads();
            const float4* W4 = (const float4*)(W3 + (ph + 1) * 4096);
            float4* Ws4 = (float4*)Ws;
#pragma unroll
            for (int i = 0; i < 8; i++) Ws4[tid + 128 * i] = W4[tid + 128 * i];
            __syncthreads();
        }
    }

    float s[8], q[8];
#pragma unroll
    for (int j = 0; j < 8; j++) { s[j] = 0.f; q[j] = 0.f; }
#pragma unroll
    for (int r = 0; r < 8; r++) {
        int row = row0 + ty * 8 + r;
        if (row >= NN) continue;
        float2 p0 = *(float2*)&acc[r][0];
        float2 p1 = *(float2*)&acc[r][1];
        float2 p2 = *(float2*)&acc[r][2];
        float2 p3 = *(float2*)&acc[r][3];
        float o[8] = {p0.x, p0.y, p1.x, p1.y, p2.x, p2.y, p3.x, p3.y};
#pragma unroll
        for (int j = 0; j < 8; j++) {
            s[j] += o[j];
            q[j] += o[j] * o[j];
        }
        ((float4*)Z)[(size_t)row * 16 + tx * 2] =
            make_float4(o[0], o[1], o[2], o[3]);
        ((float4*)Z)[(size_t)row * 16 + tx * 2 + 1] =
            make_float4(o[4], o[5], o[6], o[7]);
    }
    {
        __syncthreads();
        float* red = Xs;
#pragma unroll
        for (int j = 0; j < 8; j++) {
            int c = tx * 8 + j;
            red[c * 17 + ty] = s[j];
            red[64 * 17 + c * 17 + ty] = q[j];
        }
        __syncthreads();
        int c = tid & 63;
        int which = tid >> 6;
        float t = 0.f;
#pragma unroll
        for (int i = 0; i < 16; i++) t += red[which * 64 * 17 + c * 17 + i];
        atomicAdd(&g_red[which * 64 + c], t);
    }
}

// ============ fused attention K/V: one tile load, two GEMM phases ========
__global__ void __launch_bounds__(128, 4)
k_kv(const float* __restrict__ X, const float* __restrict__ Wv,
     const float* __restrict__ Wk, const float* __restrict__ seed) {
    __shared__ float Ws[64 * 64];
    __shared__ float Xs[128 * 64];
    int tid = threadIdx.x;
    int row0 = blockIdx.x << 7;
    int tx = tid & 7;
    int ty = tid >> 3;

    {
        const float4* W4 = (const float4*)Wv;
        float4* Ws4 = (float4*)Ws;
#pragma unroll
        for (int i = 0; i < 8; i++) Ws4[tid + 128 * i] = W4[tid + 128 * i];
    }
    {
        int c4 = tid & 15;
        int r0 = tid >> 4;
#pragma unroll
        for (int i = 0; i < 16; i++) {
            int m = r0 + 8 * i;
            int row = row0 + m;
            float4 v = make_float4(0.f, 0.f, 0.f, 0.f);
            if (row < NN) v = ((const float4*)X)[(size_t)row * 16 + c4];
            int cs = (c4 ^ (m >> 3)) & 15;
            *(float4*)&Xs[m * 64 + cs * 4] = v;
        }
    }
    __syncthreads();

    unsigned long long acc[8][4];

#pragma unroll 1
    for (int ph = 0; ph < 2; ph++) {
#pragma unroll
        for (int r = 0; r < 8; r++)
#pragma unroll
            for (int j = 0; j < 4; j++) acc[r][j] = 0ull;

#pragma unroll
        for (int k4 = 0; k4 < 16; k4++) {
            float4 xv[8];
            int cs = (k4 ^ ty) & 15;
#pragma unroll
            for (int r = 0; r < 8; r++) {
                int m = ty * 8 + r;
                xv[r] = *(const float4*)&Xs[m * 64 + cs * 4];
            }
#pragma unroll
            for (int kk = 0; kk < 4; kk++) {
                int k = k4 * 4 + kk;
                ulonglong2 w0 = *(const ulonglong2*)&Ws[k * 64 + tx * 8];
                ulonglong2 w1 = *(const ulonglong2*)&Ws[k * 64 + tx * 8 + 4];
#pragma unroll
                for (int r = 0; r < 8; r++) {
                    float xs = (kk == 0) ? xv[r].x
                             : (kk == 1) ? xv[r].y
                             : (kk == 2) ? xv[r].z : xv[r].w;
                    unsigned long long xx = bcast2(xs);
                    ffma2(acc[r][0], xx, w0.x);
                    ffma2(acc[r][1], xx, w0.y);
                    ffma2(acc[r][2], xx, w1.x);
                    ffma2(acc[r][3], xx, w1.y);
                }
            }
        }

        if (ph == 0) {
#pragma unroll
            for (int r = 0; r < 8; r++) {
                int row = row0 + ty * 8 + r;
                if (row >= NN) continue;
                float2 p0 = *(float2*)&acc[r][0];
                float2 p1 = *(float2*)&acc[r][1];
                float2 p2 = *(float2*)&acc[r][2];
                float2 p3 = *(float2*)&acc[r][3];
                ((float4*)g_agg)[(size_t)row * 16 + tx * 2] =
                    make_float4(p0.x, p0.y, p1.x, p1.y);
                ((float4*)g_agg)[(size_t)row * 16 + tx * 2 + 1] =
                    make_float4(p2.x, p2.y, p3.x, p3.y);
            }
            __syncthreads();
            const float4* W4 = (const float4*)Wk;
            float4* Ws4 = (float4*)Ws;
#pragma unroll
            for (int i = 0; i < 8; i++) Ws4[tid + 128 * i] = W4[tid + 128 * i];
            __syncthreads();
        } else {
            float sv[8];
#pragma unroll
            for (int j = 0; j < 8; j++) sv[j] = seed[tx * 8 + j];
#pragma unroll
            for (int r = 0; r < 8; r++) {
                int row = row0 + ty * 8 + r;
                float2 p0 = *(float2*)&acc[r][0];
                float2 p1 = *(float2*)&acc[r][1];
                float2 p2 = *(float2*)&acc[r][2];
                float2 p3 = *(float2*)&acc[r][3];
                float p = p0.x * sv[0] + p0.y * sv[1] + p1.x * sv[2] +
                          p1.y * sv[3] + p2.x * sv[4] + p2.y * sv[5] +
                          p3.x * sv[6] + p3.y * sv[7];
                p += __shfl_xor_sync(0xffffffffu, p, 1);
                if (row < NN && (tx & 1) == 0)
                    g_sc[row * NH + (tx >> 1)] = p * 0.25f;
            }
        }
    }
}

// ---------------- GEMM (proj) ----------------
__global__ void __launch_bounds__(128, 4)
gemm128(const float* __restrict__ X, const float* __restrict__ W,
        const float* __restrict__ bias, float* __restrict__ Y, int M, int relu,
        const float* __restrict__ inscale, const float* __restrict__ inshift) {
    __shared__ float Ws[64 * 64];
    __shared__ float Xs[128 * 64];
    int tid = threadIdx.x;
    int row0 = blockIdx.x << 7;

    {
        const float4* W4 = (const float4*)W;
        float4* Ws4 = (float4*)Ws;
#pragma unroll
        for (int i = 0; i < 8; i++) Ws4[tid + 128 * i] = W4[tid + 128 * i];
    }
    {
        int c4 = tid & 15;
        int r0 = tid >> 4;
        float4 scl = make_float4(1.f, 1.f, 1.f, 1.f);
        float4 sht = make_float4(0.f, 0.f, 0.f, 0.f);
        if (inscale) {
            scl = ((const float4*)inscale)[c4];
            sht = ((const float4*)inshift)[c4];
        }
#pragma unroll
        for (int i = 0; i < 16; i++) {
            int m = r0 + 8 * i;
            int row = row0 + m;
            float4 v = make_float4(0.f, 0.f, 0.f, 0.f);
            if (row < M) v = ((const float4*)X)[(size_t)row * 16 + c4];
            v.x = v.x * scl.x + sht.x;
            v.y = v.y * scl.y + sht.y;
            v.z = v.z * scl.z + sht.z;
            v.w = v.w * scl.w + sht.w;
            int cs = (c4 ^ (m >> 3)) & 15;
            *(float4*)&Xs[m * 64 + cs * 4] = v;
        }
    }
    __syncthreads();

    int tx = tid & 7;
    int ty = tid >> 3;

    unsigned long long acc[8][4];
#pragma unroll
    for (int r = 0; r < 8; r++)
#pragma unroll
        for (int j = 0; j < 4; j++) acc[r][j] = 0ull;

#pragma unroll
    for (int k4 = 0; k4 < 16; k4++) {
        float4 xv[8];
        int cs = (k4 ^ ty) & 15;
#pragma unroll
        for (int r = 0; r < 8; r++) {
            int m = ty * 8 + r;
            xv[r] = *(const float4*)&Xs[m * 64 + cs * 4];
        }
#pragma unroll
        for (int kk = 0; kk < 4; kk++) {
            int k = k4 * 4 + kk;
            ulonglong2 w0 = *(const ulonglong2*)&Ws[k * 64 + tx * 8];
            ulonglong2 w1 = *(const ulonglong2*)&Ws[k * 64 + tx * 8 + 4];
#pragma unroll
            for (int r = 0; r < 8; r++) {
                float xs = (kk == 0) ? xv[r].x
                         : (kk == 1) ? xv[r].y
                         : (kk == 2) ? xv[r].z : xv[r].w;
                unsigned long long xx = bcast2(xs);
                ffma2(acc[r][0], xx, w0.x);
                ffma2(acc[r][1], xx, w0.y);
                ffma2(acc[r][2], xx, w1.x);
                ffma2(acc[r][3], xx, w1.y);
            }
        }
    }

    float bv[8];
#pragma unroll
    for (int j = 0; j < 8; j++) bv[j] = 0.f;
    if (bias) {
        float4 b0 = ((const float4*)bias)[tx * 2];
        float4 b1 = ((const float4*)bias)[tx * 2 + 1];
        bv[0] = b0.x; bv[1] = b0.y; bv[2] = b0.z; bv[3] = b0.w;
        bv[4] = b1.x; bv[5] = b1.y; bv[6] = b1.z; bv[7] = b1.w;
    }

#pragma unroll
    for (int r = 0; r < 8; r++) {
        int row = row0 + ty * 8 + r;
        if (row >= M) continue;
        float o[8];
#pragma unroll
        for (int j = 0; j < 4; j++) {
            float2 p = *(float2*)&acc[r][j];
            o[2 * j] = p.x + bv[2 * j];
            o[2 * j + 1] = p.y + bv[2 * j + 1];
        }
        if (relu) {
#pragma unroll
            for (int j = 0; j < 8; j++) o[j] = fmaxf(o[j], 0.f);
        }
        ((float4*)Y)[(size_t)row * 16 + tx * 2] =
            make_float4(o[0], o[1], o[2], o[3]);
        ((float4*)Y)[(size_t)row * 16 + tx * 2 + 1] =
            make_float4(o[4], o[5], o[6], o[7]);
    }
}

// ---------------- attention readout: one block per graph ----------------
__global__ void k_attn() {
    int g = blockIdx.x;
    int tid = threadIdx.x;  // 128
    int beg = g_goff[g], end = g_goff[g + 1];
    __shared__ float shm[4 * 4];
    __shared__ float shs[4 * 4];
    __shared__ float mx[4], sm[4];
    __shared__ float pacc[64];

    float m0 = -1e30f, m1 = -1e30f, m2 = -1e30f, m3 = -1e30f;
    for (int n = beg + tid; n < end; n += 128) {
        float4 v = ((const float4*)g_sc)[n];
        m0 = fmaxf(m0, v.x); m1 = fmaxf(m1, v.y);
        m2 = fmaxf(m2, v.z); m3 = fmaxf(m3, v.w);
    }
#pragma unroll
    for (int o = 16; o; o >>= 1) {
        m0 = fmaxf(m0, __shfl_xor_sync(0xffffffffu, m0, o));
        m1 = fmaxf(m1, __shfl_xor_sync(0xffffffffu, m1, o));
        m2 = fmaxf(m2, __shfl_xor_sync(0xffffffffu, m2, o));
        m3 = fmaxf(m3, __shfl_xor_sync(0xffffffffu, m3, o));
    }
    if ((tid & 31) == 0) {
        int w = tid >> 5;
        shm[w * 4 + 0] = m0; shm[w * 4 + 1] = m1;
        shm[w * 4 + 2] = m2; shm[w * 4 + 3] = m3;
    }
    __syncthreads();
    if (tid < 4) {
        mx[tid] = fmaxf(fmaxf(shm[tid], shm[4 + tid]),
                        fmaxf(shm[8 + tid], shm[12 + tid]));
    }
    __syncthreads();

    float s0 = 0.f, s1 = 0.f, s2 = 0.f, s3 = 0.f;
    float q0 = mx[0], q1 = mx[1], q2 = mx[2], q3 = mx[3];
    for (int n = beg + tid; n < end; n += 128) {
        float4 v = ((const float4*)g_sc)[n];
        v.x = expf(v.x - q0); v.y = expf(v.y - q1);
        v.z = expf(v.z - q2); v.w = expf(v.w - q3);
        ((float4*)g_sc)[n] = v;
        s0 += v.x; s1 += v.y; s2 += v.z; s3 += v.w;
    }
#pragma unroll
    for (int o = 16; o; o >>= 1) {
        s0 += __shfl_xor_sync(0xffffffffu, s0, o);
        s1 += __shfl_xor_sync(0xffffffffu, s1, o);
        s2 += __shfl_xor_sync(0xffffffffu, s2, o);
        s3 += __shfl_xor_sync(0xffffffffu, s3, o);
    }
    if ((tid & 31) == 0) {
        int w = tid >> 5;
        shs[w * 4 + 0] = s0; shs[w * 4 + 1] = s1;
        shs[w * 4 + 2] = s2; shs[w * 4 + 3] = s3;
    }
    __syncthreads();
    if (tid < 4) {
        float t = shs[tid] + shs[4 + tid] + shs[8 + tid] + shs[12 + tid];
        sm[tid] = (t > 0.f) ? (1.f / t) : 0.f;
    }
    if (tid < 64) pacc[tid] = 0.f;
    __syncthreads();

    int c = tid & 63;
    int half = tid >> 6;
    int hh = c >> 4;
    float acc = 0.f;
    for (int n = beg + half; n < end; n += 2) {
        float w = g_sc[n * NH + hh];
        acc += w * g_agg[(size_t)n * HD + c];
    }
    if (half == 1) atomicAdd(&pacc[c], acc);
    __syncthreads();
    if (half == 0) g_pool[g * HD + c] = (acc + pacc[c]) * sm[hh];
}

// ---- fused output: embed = pool[g] @ Wo ; logits = embed @ predW + b ----
__global__ void k_out(const float* __restrict__ Wo,
                      const float* __restrict__ predW,
                      const float* __restrict__ predb,
                      float* __restrict__ out) {
    int g = blockIdx.x;
    int t = threadIdx.x;  // 128
    __shared__ float pr[64];
    __shared__ float em[64];
    if (t < 64) pr[t] = g_pool[g * 64 + t];
    __syncthreads();
    if (t < 64) {
        float s = 0.f;
#pragma unroll
        for (int k = 0; k < 64; k++) s += pr[k] * Wo[k * 64 + t];
        em[t] = s;
        out[g * 64 + t] = s;  // embed
    }
    __syncthreads();
    {
        float s = predb[t];
#pragma unroll
        for (int k = 0; k < 64; k++) s += em[k] * predW[k * NO + t];
        out[NG * HD + g * NO + t] = s;  // logits
    }
}

// ---------------- launch ----------------
extern "C" void kernel_launch(void* const* d_in, const int* in_sizes, int n_in,
                              void* d_out, int out_size) {
    const float* x = (const float*)d_in[0];
    const int* ei = (const int*)d_in[1];
    const int* batch = (const int*)d_in[2];
    const float* fng = (const float*)d_in[3];
    const float* fnb = (const float*)d_in[4];
    const float* projW = (const float*)d_in[5];
    const float* projb = (const float*)d_in[6];
    const float* mlpW = (const float*)d_in[7];
    const float* mlpb = (const float*)d_in[8];
    const float* ng = (const float*)d_in[9];
    const float* nb = (const float*)d_in[10];
    const float* seed = (const float*)d_in[11];
    const float* Wk = (const float*)d_in[12];
    const float* Wv = (const float*)d_in[13];
    const float* Wo = (const float*)d_in[14];
    const float* predW = (const float*)d_in[15];
    const float* predb = (const float*)d_in[16];
    float* out = (float*)d_out;

    float *h, *agg, *z, *bns, *bnt;
    cudaGetSymbolAddress((void**)&h, g_h);
    cudaGetSymbolAddress((void**)&agg, g_agg);
    cudaGetSymbolAddress((void**)&z, g_z);
    cudaGetSymbolAddress((void**)&bns, g_bns);
    cudaGetSymbolAddress((void**)&bnt, g_bnt);

    const int* src = ei;
    const int* dst = ei + NE;

    const int GB = (NN + 127) / 128;       // 782
    const int EW = (NN * 16 + 255) / 256;
    const int EB = (NE + 255) / 256;
    const int NB = (NN + 255) / 256;
    const int GTB = (NN * 16 + 255) / 256;
    const int NCHUNK = (NN + 1023) / 1024;

    // proj GEMM kept at launch index 3 for the profiler.
    k_bn_stats<<<256, 256>>>(x);              // also zeroes g_deg
    k_goff<<<NB, 256>>>(batch);
    k_bn_finalize<<<1, 64>>>(fng, fnb, 0);
    gemm128<<<GB, 128>>>(x, projW, projb, h, NN, 1, bns, bnt);
    k_csr_count<<<EB, 256>>>(dst);
    k_scan_chunk<<<NCHUNK, 256>>>();
    k_scan_tops<<<1, 128>>>(NCHUNK);
    k_scan_final<<<NB, 256>>>();
    k_csr_fill<<<EB, 256>>>(src, dst);

    for (int m = 0; m < 4; m++) {
        const float* Wm = mlpW + m * 3 * 4096;
        const float* bm = mlpb + m * 3 * 64;
        // c = 0: gather(h, plain) -> agg ; fused MLP agg -> z (+BN stats)
        k_gather<<<GTB, 256>>>(h, 0);
        k_mlp3<<<GB, 128>>>(agg, Wm, bm, z);
        k_bn_finalize<<<1, 64>>>(ng + m * 64, nb + m * 64, 0);
        // c = 1: gather(bnrelu(z), slot 0) -> agg ; fused MLP -> z
        k_gather<<<GTB, 256>>>(z, 1);
        k_mlp3<<<GB, 128>>>(agg, Wm, bm, z);
        k_bn_finalize<<<1, 64>>>(ng + m * 64, nb + m * 64, 1);
        // h = relu(bn(z)) + h
        k_resid_fused<<<EW, 256>>>();
    }

    // attention: fused K/V (V -> agg, scores -> g_sc; one tile load)
    k_kv<<<GB, 128>>>(h, Wv, Wk, seed);
    k_attn<<<NG, 128>>>();

    // fused output: embed + logits
    k_out<<<NG, 128>>>(Wo, predW, predb, out);
}